// round 1
// baseline (speedup 1.0000x reference)
#include <cuda_runtime.h>
#include <math.h>

// ---------------------------------------------------------------------------
// Problem constants
// ---------------------------------------------------------------------------
#define Bc    64
#define Tc    334
#define Fc    1024
#define Uc    1024
#define Ac    64
#define NBc   255
#define NTOK  (Bc * Tc)        // 21376 = 167 * 128
#define TM1   (Tc - 1)         // 333
#define NLOSS (Bc * TM1)       // 21312
#define LAM_C     0.95f
#define ACTENT_C  3e-4f
#define UNIMIX_A  0.00015625f  // 0.01 / 64

// ---------------------------------------------------------------------------
// Device scratch (no allocation allowed in kernel_launch)
// ---------------------------------------------------------------------------
__device__ float g_h0[(size_t)NTOK * Uc];
__device__ float g_h1[(size_t)NTOK * Uc];
__device__ float g_vlog[(size_t)NTOK * NBc];
__device__ float g_slog[(size_t)NTOK * NBc];
__device__ float g_plog[(size_t)NTOK * Ac];
__device__ float g_smean[NTOK];
__device__ float g_ret[NLOSS];
__device__ float g_wgt[NLOSS];
__device__ float g_scale[4];   // lo, hi, rscale
__device__ float g_loss[NLOSS];

// ---------------------------------------------------------------------------
// SGEMM: C[N,M] = A[N,K] @ W[K,M] (+ bias). 128x128 tile, BK=8, 8x8/thread.
// N must be a multiple of 128 (true here: 21376). M guarded.
// ---------------------------------------------------------------------------
__global__ __launch_bounds__(256) void sgemm_kernel(
    const float* __restrict__ A, const float* __restrict__ W,
    const float* __restrict__ bias, float* __restrict__ C,
    int N, int K, int M)
{
    __shared__ float As[8][128];
    __shared__ float Ws[8][128];

    const int brow = blockIdx.x * 128;
    const int bcol = blockIdx.y * 128;
    const int tid  = threadIdx.x;

    const int arow  = tid >> 1;        // 0..127
    const int acol4 = (tid & 1) * 4;   // 0 or 4
    const int wrow  = tid >> 5;        // 0..7
    const int wcol4 = (tid & 31) * 4;  // 0..124

    const int tx = tid & 15;           // col group
    const int ty = tid >> 4;           // row group

    float acc[8][8];
    #pragma unroll
    for (int i = 0; i < 8; i++)
        #pragma unroll
        for (int j = 0; j < 8; j++) acc[i][j] = 0.f;

    const bool mvec = ((M & 3) == 0);

    for (int k0 = 0; k0 < K; k0 += 8) {
        // A tile (transposed into As[k][row])
        float4 av = *(const float4*)(A + (size_t)(brow + arow) * K + k0 + acol4);
        As[acol4 + 0][arow] = av.x;
        As[acol4 + 1][arow] = av.y;
        As[acol4 + 2][arow] = av.z;
        As[acol4 + 3][arow] = av.w;
        // W tile
        int colbase = bcol + wcol4;
        if (mvec && colbase + 4 <= M) {
            *(float4*)&Ws[wrow][wcol4] =
                *(const float4*)(W + (size_t)(k0 + wrow) * M + colbase);
        } else {
            #pragma unroll
            for (int j = 0; j < 4; j++)
                Ws[wrow][wcol4 + j] =
                    (colbase + j < M) ? W[(size_t)(k0 + wrow) * M + colbase + j] : 0.f;
        }
        __syncthreads();

        #pragma unroll
        for (int kk = 0; kk < 8; kk++) {
            float4 a0 = *(const float4*)&As[kk][ty * 8];
            float4 a1 = *(const float4*)&As[kk][ty * 8 + 4];
            float4 b0 = *(const float4*)&Ws[kk][tx * 8];
            float4 b1 = *(const float4*)&Ws[kk][tx * 8 + 4];
            float ar[8] = {a0.x, a0.y, a0.z, a0.w, a1.x, a1.y, a1.z, a1.w};
            float br[8] = {b0.x, b0.y, b0.z, b0.w, b1.x, b1.y, b1.z, b1.w};
            #pragma unroll
            for (int i = 0; i < 8; i++)
                #pragma unroll
                for (int j = 0; j < 8; j++)
                    acc[i][j] = fmaf(ar[i], br[j], acc[i][j]);
        }
        __syncthreads();
    }

    #pragma unroll
    for (int i = 0; i < 8; i++) {
        int r = brow + ty * 8 + i;
        #pragma unroll
        for (int j = 0; j < 8; j++) {
            int c = bcol + tx * 8 + j;
            if (c < M) {
                float v = acc[i][j];
                if (bias) v += bias[c];
                C[(size_t)r * M + c] = v;
            }
        }
    }
}

// ---------------------------------------------------------------------------
// rmsnorm + silu, one row (1024) per block, 256 threads
// ---------------------------------------------------------------------------
__device__ __forceinline__ float silu_f(float z) { return z / (1.f + expf(-z)); }

__global__ __launch_bounds__(256) void rmsnorm_silu_kernel(
    const float* __restrict__ X, const float* __restrict__ g, float* __restrict__ Y)
{
    int row = blockIdx.x;
    int t = threadIdx.x;
    const float4* x4 = (const float4*)(X + (size_t)row * Uc);
    float4 xv = x4[t];
    float ss = xv.x * xv.x + xv.y * xv.y + xv.z * xv.z + xv.w * xv.w;
    #pragma unroll
    for (int o = 16; o; o >>= 1) ss += __shfl_xor_sync(0xffffffffu, ss, o);
    __shared__ float sh[8];
    if ((t & 31) == 0) sh[t >> 5] = ss;
    __syncthreads();
    if (t < 32) {
        float v = (t < 8) ? sh[t] : 0.f;
        #pragma unroll
        for (int o = 4; o; o >>= 1) v += __shfl_xor_sync(0xffffffffu, v, o);
        if (t == 0) sh[0] = v;
    }
    __syncthreads();
    float r = rsqrtf(sh[0] * (1.0f / (float)Uc) + 1e-6f);
    float4 gv = ((const float4*)g)[t];
    float4 o;
    o.x = silu_f(xv.x * r * gv.x);
    o.y = silu_f(xv.y * r * gv.y);
    o.z = silu_f(xv.z * r * gv.z);
    o.w = silu_f(xv.w * r * gv.w);
    ((float4*)(Y + (size_t)row * Uc))[t] = o;
}

// ---------------------------------------------------------------------------
// symexp bin helper (matches symexp(linspace(-20,20,255)))
// ---------------------------------------------------------------------------
__device__ __forceinline__ float bin_val(int i) {
    float u = -20.0f + (40.0f / 254.0f) * (float)i;
    return copysignf(expm1f(fabsf(u)), u);
}

// ---------------------------------------------------------------------------
// slow_mean: per-token softmax(slow_logits) . bins  (double-accumulated)
// ---------------------------------------------------------------------------
__global__ __launch_bounds__(256) void slowmean_kernel(
    const float* __restrict__ slog, float* __restrict__ smean)
{
    __shared__ float sred[8];
    __shared__ double dden[8], dnum[8];
    int row = blockIdx.x, tid = threadIdx.x;
    float lg = -3.4e38f, bn = 0.f;
    if (tid < NBc) {
        lg = slog[(size_t)row * NBc + tid];
        bn = bin_val(tid);
    }
    float m = lg;
    #pragma unroll
    for (int o = 16; o; o >>= 1) m = fmaxf(m, __shfl_xor_sync(0xffffffffu, m, o));
    if ((tid & 31) == 0) sred[tid >> 5] = m;
    __syncthreads();
    if (tid < 32) {
        float v = (tid < 8) ? sred[tid] : -3.4e38f;
        #pragma unroll
        for (int o = 4; o; o >>= 1) v = fmaxf(v, __shfl_xor_sync(0xffffffffu, v, o));
        if (tid == 0) sred[0] = v;
    }
    __syncthreads();
    float M = sred[0];
    float e = (tid < NBc) ? expf(lg - M) : 0.f;
    double den = (double)e;
    double num = (double)e * (double)bn;
    #pragma unroll
    for (int o = 16; o; o >>= 1) {
        den += __shfl_xor_sync(0xffffffffu, den, o);
        num += __shfl_xor_sync(0xffffffffu, num, o);
    }
    if ((tid & 31) == 0) { dden[tid >> 5] = den; dnum[tid >> 5] = num; }
    __syncthreads();
    if (tid == 0) {
        double D = 0, Nn = 0;
        #pragma unroll
        for (int i = 0; i < 8; i++) { D += dden[i]; Nn += dnum[i]; }
        smean[row] = (float)(Nn / D);
    }
}

// ---------------------------------------------------------------------------
// weight cumprod + reverse lambda-return scan. 1 block, 64 threads (1/row).
// ---------------------------------------------------------------------------
__global__ void lamret_kernel(
    const float* __restrict__ reward, const float* __restrict__ cont,
    const float* __restrict__ smean, float* __restrict__ ret, float* __restrict__ wgt)
{
    int b = threadIdx.x;
    if (b >= Bc) return;
    float acc = 1.f;
    for (int t = 0; t < TM1; t++) {
        acc *= cont[b * Tc + t];
        wgt[b * TM1 + t] = acc;
    }
    float r = smean[b * Tc + (Tc - 1)];
    for (int t = TM1 - 1; t >= 0; t--) {
        float live = cont[b * Tc + t + 1];
        float interm = reward[b * Tc + t + 1] + (1.f - LAM_C) * live * smean[b * Tc + t + 1];
        r = interm + live * LAM_C * r;
        ret[b * TM1 + t] = r;
    }
}

// ---------------------------------------------------------------------------
// percentile(5, 95) of ret via single-block bitonic sort (padded to 32768)
// ---------------------------------------------------------------------------
__global__ void percentile_kernel(const float* __restrict__ ret, float* __restrict__ scale)
{
    extern __shared__ float s[];
    const int PAD = 32768;
    for (int i = threadIdx.x; i < PAD; i += blockDim.x)
        s[i] = (i < NLOSS) ? ret[i] : 3.4e38f;
    __syncthreads();
    for (int ksz = 2; ksz <= PAD; ksz <<= 1) {
        for (int j = ksz >> 1; j > 0; j >>= 1) {
            for (int a = threadIdx.x; a < PAD; a += blockDim.x) {
                int p = a ^ j;
                if (p > a) {
                    bool asc = ((a & ksz) == 0);
                    float x = s[a], y = s[p];
                    if ((x > y) == asc) { s[a] = y; s[p] = x; }
                }
            }
            __syncthreads();
        }
    }
    if (threadIdx.x == 0) {
        double p5 = 0.05 * (double)(NLOSS - 1);
        double p95 = 0.95 * (double)(NLOSS - 1);
        int i5 = (int)p5, i95 = (int)p95;
        float f5 = (float)(p5 - i5), f95 = (float)(p95 - i95);
        float lo = s[i5] + f5 * (s[i5 + 1] - s[i5]);
        float hi = s[i95] + f95 * (s[i95 + 1] - s[i95]);
        scale[0] = lo;
        scale[1] = hi;
        scale[2] = fmaxf(hi - lo, 1.0f);
    }
}

// ---------------------------------------------------------------------------
// per-token loss (policy + value), one block per (b, t<T-1)
// ---------------------------------------------------------------------------
__device__ __forceinline__ float twohot_nll(const float* svl, const float* sbins,
                                            float logZ, float y)
{
    y = fminf(fmaxf(y, sbins[0]), sbins[NBc - 1]);
    int lo = 0, hi = NBc - 1;
    while (hi > lo) {
        int mid = (lo + hi) >> 1;
        if (sbins[mid] >= y) hi = mid; else lo = mid + 1;
    }
    int k = hi - 1;
    if (k < 0) k = 0;
    if (k > NBc - 2) k = NBc - 2;
    float bl = sbins[k], bh = sbins[k + 1];
    float w = (y - bl) / (bh - bl);
    w = fminf(fmaxf(w, 0.f), 1.f);
    float l0 = svl[k] - logZ, l1 = svl[k + 1] - logZ;
    return -((1.f - w) * l0 + w * l1);
}

__global__ __launch_bounds__(256) void loss_kernel(
    const float* __restrict__ vlog, const float* __restrict__ plog,
    const float* __restrict__ smean, const float* __restrict__ ret,
    const float* __restrict__ wgt, const int* __restrict__ act,
    const float* __restrict__ scale, float* __restrict__ loss)
{
    __shared__ float sbins[NBc];
    __shared__ float svl[NBc];
    __shared__ float sred[8];
    __shared__ float sres[4];  // [0]=max/logZ, [1]=ent, [2]=logpi

    int i = blockIdx.x;
    int b = i / TM1, t = i - b * TM1;
    int row = b * Tc + t;
    int tid = threadIdx.x;

    if (tid < NBc) {
        sbins[tid] = bin_val(tid);
        svl[tid] = vlog[(size_t)row * NBc + tid];
    }
    __syncthreads();

    // max over value logits
    float v = (tid < NBc) ? svl[tid] : -3.4e38f;
    #pragma unroll
    for (int o = 16; o; o >>= 1) v = fmaxf(v, __shfl_xor_sync(0xffffffffu, v, o));
    if ((tid & 31) == 0) sred[tid >> 5] = v;
    __syncthreads();
    if (tid < 32) {
        float m = (tid < 8) ? sred[tid] : -3.4e38f;
        #pragma unroll
        for (int o = 4; o; o >>= 1) m = fmaxf(m, __shfl_xor_sync(0xffffffffu, m, o));
        if (tid == 0) sres[0] = m;
    }
    __syncthreads();
    float M = sres[0];
    float e = (tid < NBc) ? expf(svl[tid] - M) : 0.f;
    #pragma unroll
    for (int o = 16; o; o >>= 1) e += __shfl_xor_sync(0xffffffffu, e, o);
    if ((tid & 31) == 0) sred[tid >> 5] = e;
    __syncthreads();
    if (tid < 32) {
        float s = (tid < 8) ? sred[tid] : 0.f;
        #pragma unroll
        for (int o = 4; o; o >>= 1) s += __shfl_xor_sync(0xffffffffu, s, o);
        if (tid == 0) sres[0] = M + logf(s);   // logZ
    }
    __syncthreads();
    float logZ = sres[0];

    // policy softmax + unimix in warp 0 (A=64, 2 per lane)
    if (tid < 32) {
        float p0 = plog[(size_t)row * Ac + tid];
        float p1 = plog[(size_t)row * Ac + tid + 32];
        float m = fmaxf(p0, p1);
        #pragma unroll
        for (int o = 16; o; o >>= 1) m = fmaxf(m, __shfl_xor_sync(0xffffffffu, m, o));
        float e0 = expf(p0 - m), e1 = expf(p1 - m);
        float s = e0 + e1;
        #pragma unroll
        for (int o = 16; o; o >>= 1) s += __shfl_xor_sync(0xffffffffu, s, o);
        float inv = 1.0f / s;
        float pr0 = 0.99f * e0 * inv + UNIMIX_A;
        float pr1 = 0.99f * e1 * inv + UNIMIX_A;
        float lp0 = logf(pr0), lp1 = logf(pr1);
        float entp = -(pr0 * lp0 + pr1 * lp1);
        #pragma unroll
        for (int o = 16; o; o >>= 1) entp += __shfl_xor_sync(0xffffffffu, entp, o);
        int a = act[row];
        float lpi = (a == tid) ? lp0 : ((a == tid + 32) ? lp1 : 0.f);
        #pragma unroll
        for (int o = 16; o; o >>= 1) lpi += __shfl_xor_sync(0xffffffffu, lpi, o);
        if (tid == 0) { sres[1] = entp; sres[2] = lpi; }
    }
    __syncthreads();

    if (tid == 0) {
        float reti = ret[i];
        float sm = smean[row];
        float rscale = scale[2];
        float adv = (reti - sm) / rscale;
        float wt = wgt[i];
        float pl = wt * -(sres[2] * adv + ACTENT_C * sres[1]);
        float vl = twohot_nll(svl, sbins, logZ, reti) + twohot_nll(svl, sbins, logZ, sm);
        loss[i] = pl + wt * vl;
    }
}

// ---------------------------------------------------------------------------
// deterministic final reduction: total = sum(loss) / NLOSS
// ---------------------------------------------------------------------------
__global__ __launch_bounds__(1024) void reduce_kernel(
    const float* __restrict__ loss, float* __restrict__ out)
{
    __shared__ double sd[32];
    double s = 0.0;
    for (int i = threadIdx.x; i < NLOSS; i += 1024) s += (double)loss[i];
    #pragma unroll
    for (int o = 16; o; o >>= 1) s += __shfl_xor_sync(0xffffffffu, s, o);
    if ((threadIdx.x & 31) == 0) sd[threadIdx.x >> 5] = s;
    __syncthreads();
    if (threadIdx.x == 0) {
        double tot = 0.0;
        #pragma unroll
        for (int w = 0; w < 32; w++) tot += sd[w];
        out[0] = (float)(tot / (double)NLOSS);
    }
}

// ---------------------------------------------------------------------------
// host: kernel_launch
// ---------------------------------------------------------------------------
static void run_mlp_net(const float* feat, const float* W_in, const float* W_hid,
                        const float* gn, const float* Hw, const float* Hb,
                        float* h0, float* h1, float* outLogits, int M)
{
    dim3 gU(NTOK / 128, Uc / 128);
    sgemm_kernel<<<gU, 256>>>(feat, W_in, nullptr, h0, NTOK, Fc, Uc);
    rmsnorm_silu_kernel<<<NTOK, 256>>>(h0, gn, h0);
    float* cur = h0;
    float* nxt = h1;
    for (int i = 0; i < 4; i++) {
        sgemm_kernel<<<gU, 256>>>(cur, W_hid + (size_t)i * Uc * Uc, nullptr, nxt,
                                  NTOK, Uc, Uc);
        rmsnorm_silu_kernel<<<NTOK, 256>>>(nxt, gn + (size_t)(i + 1) * Uc, nxt);
        float* tmp = cur; cur = nxt; nxt = tmp;
    }
    dim3 gH(NTOK / 128, (M + 127) / 128);
    sgemm_kernel<<<gH, 256>>>(cur, Hw, Hb, outLogits, NTOK, Uc, M);
}

extern "C" void kernel_launch(void* const* d_in, const int* in_sizes, int n_in,
                              void* d_out, int out_size)
{
    const float* feat   = (const float*)d_in[0];
    const float* reward = (const float*)d_in[1];
    const float* cont   = (const float*)d_in[2];
    const int*   act    = (const int*)  d_in[3];
    const float* pW_in  = (const float*)d_in[4];
    const float* pW_hid = (const float*)d_in[5];
    const float* p_gn   = (const float*)d_in[6];
    const float* pHw    = (const float*)d_in[7];
    const float* pHb    = (const float*)d_in[8];
    const float* vW_in  = (const float*)d_in[9];
    const float* vW_hid = (const float*)d_in[10];
    const float* v_gn   = (const float*)d_in[11];
    const float* vHw    = (const float*)d_in[12];
    const float* vHb    = (const float*)d_in[13];
    const float* sW_in  = (const float*)d_in[14];
    const float* sW_hid = (const float*)d_in[15];
    const float* s_gn   = (const float*)d_in[16];
    const float* sHw    = (const float*)d_in[17];
    const float* sHb    = (const float*)d_in[18];

    float *h0, *h1, *vlog, *slog, *plg, *smean, *ret, *wgt, *scale, *loss;
    cudaGetSymbolAddress((void**)&h0, g_h0);
    cudaGetSymbolAddress((void**)&h1, g_h1);
    cudaGetSymbolAddress((void**)&vlog, g_vlog);
    cudaGetSymbolAddress((void**)&slog, g_slog);
    cudaGetSymbolAddress((void**)&plg, g_plog);
    cudaGetSymbolAddress((void**)&smean, g_smean);
    cudaGetSymbolAddress((void**)&ret, g_ret);
    cudaGetSymbolAddress((void**)&wgt, g_wgt);
    cudaGetSymbolAddress((void**)&scale, g_scale);
    cudaGetSymbolAddress((void**)&loss, g_loss);

    cudaFuncSetAttribute(percentile_kernel,
                         cudaFuncAttributeMaxDynamicSharedMemorySize, 131072);

    // value net -> vlog, slow net -> slog, policy net -> plg
    run_mlp_net(feat, vW_in, vW_hid, v_gn, vHw, vHb, h0, h1, vlog, NBc);
    run_mlp_net(feat, sW_in, sW_hid, s_gn, sHw, sHb, h0, h1, slog, NBc);
    slowmean_kernel<<<NTOK, 256>>>(slog, smean);
    run_mlp_net(feat, pW_in, pW_hid, p_gn, pHw, pHb, h0, h1, plg, Ac);

    lamret_kernel<<<1, 64>>>(reward, cont, smean, ret, wgt);
    percentile_kernel<<<1, 1024, 131072>>>(ret, scale);
    loss_kernel<<<NLOSS, 256>>>(vlog, plg, smean, ret, wgt, act, scale, loss);
    reduce_kernel<<<1, 1024>>>(loss, (float*)d_out);
}

// round 3
// speedup vs baseline: 2.6206x; 2.6206x over previous
#include <cuda_runtime.h>
#include <cuda_bf16.h>
#include <math.h>
#include <stdint.h>

// ---------------------------------------------------------------------------
// Problem constants
// ---------------------------------------------------------------------------
#define Bc    64
#define Tc    334
#define Fc    1024
#define Uc    1024
#define Ac    64
#define NBc   255
#define NTOK  (Bc * Tc)        // 21376 = 167 * 128
#define TM1   (Tc - 1)         // 333
#define NLOSS (Bc * TM1)       // 21312
#define LAM_C     0.95f
#define ACTENT_C  3e-4f
#define UNIMIX_A  0.00015625f  // 0.01 / 64
#define NCH   32               // K chunks of 32 (K = 1024)

// smem tile geometry: 128 rows x 32 cols bf16, stride 40 elements (80 B)
#define TSTRIDE 40
#define TILE_B  (128 * TSTRIDE * 2)          // 10240 bytes
#define STAGE_B (4 * TILE_B)                 // Ahi,Alo,Bhi,Blo
#define SMEM_B  (2 * STAGE_B)                // 81920 bytes

// ---------------------------------------------------------------------------
// Device scratch
// ---------------------------------------------------------------------------
__device__ float g_h0[(size_t)NTOK * Uc];
__device__ float g_h1[(size_t)NTOK * Uc];
__device__ float g_vlog[(size_t)NTOK * NBc];
__device__ float g_slog[(size_t)NTOK * NBc];
__device__ float g_plog[(size_t)NTOK * Ac];
__device__ float g_smean[NTOK];
__device__ float g_ret[NLOSS];
__device__ float g_wgt[NLOSS];
__device__ float g_scale[4];
__device__ float g_loss[NLOSS];
// K-major (transposed) fp32 weights. Head buffers padded; pad rows are never
// written and stay zero from static initialization.
__device__ float g_wtA_v[5ull * 1024 * 1024];
__device__ float g_wtA_s[5ull * 1024 * 1024];
__device__ float g_wtA_p[5ull * 1024 * 1024];
__device__ float g_wtH_v[256 * 1024];
__device__ float g_wtH_s[256 * 1024];
__device__ float g_wtH_p[128 * 1024];

// ---------------------------------------------------------------------------
// helpers
// ---------------------------------------------------------------------------
__device__ __forceinline__ uint32_t smem_u32(const void* p) {
    uint32_t a;
    asm("{ .reg .u64 t; cvta.to.shared.u64 t, %1; cvt.u32.u64 %0, t; }" : "=r"(a) : "l"(p));
    return a;
}

__device__ __forceinline__ void ldm_x4(uint32_t* f, uint32_t addr) {
    asm volatile("ldmatrix.sync.aligned.m8n8.x4.shared.b16 {%0,%1,%2,%3}, [%4];"
                 : "=r"(f[0]), "=r"(f[1]), "=r"(f[2]), "=r"(f[3]) : "r"(addr));
}

__device__ __forceinline__ void mma_bf16(float* c, const uint32_t* a,
                                         uint32_t b0, uint32_t b1) {
    asm volatile(
        "mma.sync.aligned.m16n8k16.row.col.f32.bf16.bf16.f32 "
        "{%0,%1,%2,%3}, {%4,%5,%6,%7}, {%8,%9}, {%0,%1,%2,%3};"
        : "+f"(c[0]), "+f"(c[1]), "+f"(c[2]), "+f"(c[3])
        : "r"(a[0]), "r"(a[1]), "r"(a[2]), "r"(a[3]), "r"(b0), "r"(b1));
}

// split fp32 -> (hi, lo) bf16 pairs packed as uint2 (4 consecutive k values)
__device__ __forceinline__ void split4(float4 v, uint2& hi, uint2& lo) {
    __nv_bfloat16 hx = __float2bfloat16(v.x);
    __nv_bfloat16 hy = __float2bfloat16(v.y);
    __nv_bfloat16 hz = __float2bfloat16(v.z);
    __nv_bfloat16 hw = __float2bfloat16(v.w);
    __nv_bfloat16 lx = __float2bfloat16(v.x - __bfloat162float(hx));
    __nv_bfloat16 ly = __float2bfloat16(v.y - __bfloat162float(hy));
    __nv_bfloat16 lz = __float2bfloat16(v.z - __bfloat162float(hz));
    __nv_bfloat16 lw = __float2bfloat16(v.w - __bfloat162float(hw));
    __nv_bfloat162 h0 = __nv_bfloat162(hx, hy), h1 = __nv_bfloat162(hz, hw);
    __nv_bfloat162 l0 = __nv_bfloat162(lx, ly), l1 = __nv_bfloat162(lz, lw);
    hi.x = *(uint32_t*)&h0; hi.y = *(uint32_t*)&h1;
    lo.x = *(uint32_t*)&l0; lo.y = *(uint32_t*)&l1;
}

// ---------------------------------------------------------------------------
// bf16x3-split tensor-core GEMM: C[NTOK, Mout] = A[NTOK,1024] @ Bt^T (+bias)
// Bt is K-major [row = out-col][1024]; rows padded to >= gridDim.y*128.
// ---------------------------------------------------------------------------
__global__ __launch_bounds__(256) void tc_gemm(
    const float* __restrict__ A, const float* __restrict__ Bt,
    const float* __restrict__ bias, float* __restrict__ C, int Mout)
{
    extern __shared__ char smem[];
    const uint32_t sb = smem_u32(smem);
    const int tid = threadIdx.x;
    const int lane = tid & 31;
    const int warp = tid >> 5;
    const int brow = blockIdx.x * 128;
    const int bcol = blockIdx.y * 128;

    const int wm = warp >> 1;          // 0..3 -> m offset wm*32
    const int wn = warp & 1;           // 0..1 -> n offset wn*64
    const int m0w = wm * 32;
    const int n0w = wn * 64;

    // per-thread load indices: 1024 float4 slots per operand tile
    // idx = tid + 256*i ; row = idx>>3 ; c4 = idx&7 (col = c4*4)
    float4 stA[4], stB[4];

    float c[2][8][4];
    #pragma unroll
    for (int i = 0; i < 2; i++)
        #pragma unroll
        for (int j = 0; j < 8; j++)
            #pragma unroll
            for (int q = 0; q < 4; q++) c[i][j][q] = 0.f;

    auto load_regs = [&](int ch) {
        const int k0 = ch * 32;
        #pragma unroll
        for (int i = 0; i < 4; i++) {
            int idx = tid + 256 * i;
            int r = idx >> 3, c4 = idx & 7;
            stA[i] = *(const float4*)(A + (size_t)(brow + r) * 1024 + k0 + c4 * 4);
            stB[i] = *(const float4*)(Bt + (size_t)(bcol + r) * 1024 + k0 + c4 * 4);
        }
    };
    auto write_smem = [&](int buf) {
        const uint32_t base = (uint32_t)buf * STAGE_B;
        #pragma unroll
        for (int i = 0; i < 4; i++) {
            int idx = tid + 256 * i;
            int r = idx >> 3, c4 = idx & 7;
            uint32_t off = (uint32_t)(r * TSTRIDE + c4 * 4) * 2;
            uint2 hi, lo;
            split4(stA[i], hi, lo);
            *(uint2*)(smem + base + off) = hi;              // Ahi
            *(uint2*)(smem + base + TILE_B + off) = lo;     // Alo
            split4(stB[i], hi, lo);
            *(uint2*)(smem + base + 2 * TILE_B + off) = hi; // Bhi
            *(uint2*)(smem + base + 3 * TILE_B + off) = lo; // Blo
        }
    };

    // ldmatrix lane addressing (x4, non-trans): row = r0 + (lane&15),
    // col = k0 + 8*(lane>>4)
    const int lrow = lane & 15;
    const int lcol8 = (lane >> 4) << 3;

    load_regs(0);
    write_smem(0);
    __syncthreads();

    for (int ch = 0; ch < NCH; ch++) {
        const int buf = ch & 1;
        if (ch + 1 < NCH) load_regs(ch + 1);

        const uint32_t base = sb + (uint32_t)buf * STAGE_B;
        #pragma unroll
        for (int ss = 0; ss < 2; ss++) {
            const int kk = ss * 16;
            uint32_t aHi[2][4], aLo[2][4];
            #pragma unroll
            for (int i = 0; i < 2; i++) {
                uint32_t ar = base +
                    (uint32_t)((m0w + i * 16 + lrow) * TSTRIDE + kk + lcol8) * 2;
                ldm_x4(aHi[i], ar);
                ldm_x4(aLo[i], ar + TILE_B);
            }
            #pragma unroll
            for (int g = 0; g < 4; g++) {
                uint32_t br = base + 2 * TILE_B +
                    (uint32_t)((n0w + g * 16 + lrow) * TSTRIDE + kk + lcol8) * 2;
                uint32_t bH[4], bL[4];
                ldm_x4(bH, br);
                ldm_x4(bL, br + TILE_B);
                #pragma unroll
                for (int i = 0; i < 2; i++) {
                    mma_bf16(c[i][2 * g],     aHi[i], bH[0], bH[2]);
                    mma_bf16(c[i][2 * g + 1], aHi[i], bH[1], bH[3]);
                    mma_bf16(c[i][2 * g],     aLo[i], bH[0], bH[2]);
                    mma_bf16(c[i][2 * g + 1], aLo[i], bH[1], bH[3]);
                    mma_bf16(c[i][2 * g],     aHi[i], bL[0], bL[2]);
                    mma_bf16(c[i][2 * g + 1], aHi[i], bL[1], bL[3]);
                }
            }
        }

        if (ch + 1 < NCH) {
            write_smem(buf ^ 1);
            __syncthreads();
        }
    }

    // epilogue
    const int r = lane >> 2;
    const int cc = 2 * (lane & 3);
    #pragma unroll
    for (int i = 0; i < 2; i++) {
        int rowb = brow + m0w + i * 16;
        #pragma unroll
        for (int j = 0; j < 8; j++) {
            int col = bcol + n0w + j * 8 + cc;
            float b0 = 0.f, b1 = 0.f;
            if (bias) {
                if (col < Mout) b0 = bias[col];
                if (col + 1 < Mout) b1 = bias[col + 1];
            }
            float* p0 = C + (size_t)(rowb + r) * Mout + col;
            float* p1 = C + (size_t)(rowb + r + 8) * Mout + col;
            if (col + 1 < Mout) {
                p0[0] = c[i][j][0] + b0; p0[1] = c[i][j][1] + b1;
                p1[0] = c[i][j][2] + b0; p1[1] = c[i][j][3] + b1;
            } else if (col < Mout) {
                p0[0] = c[i][j][0] + b0;
                p1[0] = c[i][j][2] + b0;
            }
        }
    }
}

// ---------------------------------------------------------------------------
// weight transpose: W[1024, M] -> Wt[M, 1024] (K-major)
// ---------------------------------------------------------------------------
__global__ __launch_bounds__(256) void transpose_kernel(
    const float* __restrict__ W, float* __restrict__ Wt, int M)
{
    __shared__ float t[32][33];
    int k0 = blockIdx.x * 32, m0 = blockIdx.y * 32;
    int x = threadIdx.x, y = threadIdx.y;   // 32 x 8
    #pragma unroll
    for (int j = 0; j < 32; j += 8) {
        int m = m0 + x;
        if (m < M) t[y + j][x] = W[(size_t)(k0 + y + j) * M + m];
    }
    __syncthreads();
    #pragma unroll
    for (int j = 0; j < 32; j += 8) {
        int m = m0 + y + j;
        if (m < M) Wt[(size_t)m * 1024 + k0 + x] = t[x][y + j];
    }
}

// ---------------------------------------------------------------------------
// rmsnorm + silu
// ---------------------------------------------------------------------------
__device__ __forceinline__ float silu_f(float z) { return z / (1.f + expf(-z)); }

__global__ __launch_bounds__(256) void rmsnorm_silu_kernel(
    const float* __restrict__ X, const float* __restrict__ g, float* __restrict__ Y)
{
    int row = blockIdx.x;
    int t = threadIdx.x;
    const float4* x4 = (const float4*)(X + (size_t)row * Uc);
    float4 xv = x4[t];
    float ss = xv.x * xv.x + xv.y * xv.y + xv.z * xv.z + xv.w * xv.w;
    #pragma unroll
    for (int o = 16; o; o >>= 1) ss += __shfl_xor_sync(0xffffffffu, ss, o);
    __shared__ float sh[8];
    if ((t & 31) == 0) sh[t >> 5] = ss;
    __syncthreads();
    if (t < 32) {
        float v = (t < 8) ? sh[t] : 0.f;
        #pragma unroll
        for (int o = 4; o; o >>= 1) v += __shfl_xor_sync(0xffffffffu, v, o);
        if (t == 0) sh[0] = v;
    }
    __syncthreads();
    float r = rsqrtf(sh[0] * (1.0f / (float)Uc) + 1e-6f);
    float4 gv = ((const float4*)g)[t];
    float4 o;
    o.x = silu_f(xv.x * r * gv.x);
    o.y = silu_f(xv.y * r * gv.y);
    o.z = silu_f(xv.z * r * gv.z);
    o.w = silu_f(xv.w * r * gv.w);
    ((float4*)(Y + (size_t)row * Uc))[t] = o;
}

// ---------------------------------------------------------------------------
// symexp bins
// ---------------------------------------------------------------------------
__device__ __forceinline__ float bin_val(int i) {
    float u = -20.0f + (40.0f / 254.0f) * (float)i;
    return copysignf(expm1f(fabsf(u)), u);
}

// ---------------------------------------------------------------------------
// slow_mean
// ---------------------------------------------------------------------------
__global__ __launch_bounds__(256) void slowmean_kernel(
    const float* __restrict__ slog, float* __restrict__ smean)
{
    __shared__ float sred[8];
    __shared__ double dden[8], dnum[8];
    int row = blockIdx.x, tid = threadIdx.x;
    float lg = -3.4e38f, bn = 0.f;
    if (tid < NBc) {
        lg = slog[(size_t)row * NBc + tid];
        bn = bin_val(tid);
    }
    float m = lg;
    #pragma unroll
    for (int o = 16; o; o >>= 1) m = fmaxf(m, __shfl_xor_sync(0xffffffffu, m, o));
    if ((tid & 31) == 0) sred[tid >> 5] = m;
    __syncthreads();
    if (tid < 32) {
        float v = (tid < 8) ? sred[tid] : -3.4e38f;
        #pragma unroll
        for (int o = 4; o; o >>= 1) v = fmaxf(v, __shfl_xor_sync(0xffffffffu, v, o));
        if (tid == 0) sred[0] = v;
    }
    __syncthreads();
    float M = sred[0];
    float e = (tid < NBc) ? expf(lg - M) : 0.f;
    double den = (double)e;
    double num = (double)e * (double)bn;
    #pragma unroll
    for (int o = 16; o; o >>= 1) {
        den += __shfl_xor_sync(0xffffffffu, den, o);
        num += __shfl_xor_sync(0xffffffffu, num, o);
    }
    if ((tid & 31) == 0) { dden[tid >> 5] = den; dnum[tid >> 5] = num; }
    __syncthreads();
    if (tid == 0) {
        double D = 0, Nn = 0;
        #pragma unroll
        for (int i = 0; i < 8; i++) { D += dden[i]; Nn += dnum[i]; }
        smean[row] = (float)(Nn / D);
    }
}

// ---------------------------------------------------------------------------
// lambda-return scan
// ---------------------------------------------------------------------------
__global__ void lamret_kernel(
    const float* __restrict__ reward, const float* __restrict__ cont,
    const float* __restrict__ smean, float* __restrict__ ret, float* __restrict__ wgt)
{
    int b = threadIdx.x;
    if (b >= Bc) return;
    float acc = 1.f;
    for (int t = 0; t < TM1; t++) {
        acc *= cont[b * Tc + t];
        wgt[b * TM1 + t] = acc;
    }
    float r = smean[b * Tc + (Tc - 1)];
    for (int t = TM1 - 1; t >= 0; t--) {
        float live = cont[b * Tc + t + 1];
        float interm = reward[b * Tc + t + 1] + (1.f - LAM_C) * live * smean[b * Tc + t + 1];
        r = interm + live * LAM_C * r;
        ret[b * TM1 + t] = r;
    }
}

// ---------------------------------------------------------------------------
// percentile via bitonic sort
// ---------------------------------------------------------------------------
__global__ void percentile_kernel(const float* __restrict__ ret, float* __restrict__ scale)
{
    extern __shared__ float s[];
    const int PAD = 32768;
    for (int i = threadIdx.x; i < PAD; i += blockDim.x)
        s[i] = (i < NLOSS) ? ret[i] : 3.4e38f;
    __syncthreads();
    for (int ksz = 2; ksz <= PAD; ksz <<= 1) {
        for (int j = ksz >> 1; j > 0; j >>= 1) {
            for (int a = threadIdx.x; a < PAD; a += blockDim.x) {
                int p = a ^ j;
                if (p > a) {
                    bool asc = ((a & ksz) == 0);
                    float x = s[a], y = s[p];
                    if ((x > y) == asc) { s[a] = y; s[p] = x; }
                }
            }
            __syncthreads();
        }
    }
    if (threadIdx.x == 0) {
        double p5 = 0.05 * (double)(NLOSS - 1);
        double p95 = 0.95 * (double)(NLOSS - 1);
        int i5 = (int)p5, i95 = (int)p95;
        float f5 = (float)(p5 - i5), f95 = (float)(p95 - i95);
        float lo = s[i5] + f5 * (s[i5 + 1] - s[i5]);
        float hi = s[i95] + f95 * (s[i95 + 1] - s[i95]);
        scale[0] = lo;
        scale[1] = hi;
        scale[2] = fmaxf(hi - lo, 1.0f);
    }
}

// ---------------------------------------------------------------------------
// per-token loss
// ---------------------------------------------------------------------------
__device__ __forceinline__ float twohot_nll(const float* svl, const float* sbins,
                                            float logZ, float y)
{
    y = fminf(fmaxf(y, sbins[0]), sbins[NBc - 1]);
    int lo = 0, hi = NBc - 1;
    while (hi > lo) {
        int mid = (lo + hi) >> 1;
        if (sbins[mid] >= y) hi = mid; else lo = mid + 1;
    }
    int k = hi - 1;
    if (k < 0) k = 0;
    if (k > NBc - 2) k = NBc - 2;
    float bl = sbins[k], bh = sbins[k + 1];
    float w = (y - bl) / (bh - bl);
    w = fminf(fmaxf(w, 0.f), 1.f);
    float l0 = svl[k] - logZ, l1 = svl[k + 1] - logZ;
    return -((1.f - w) * l0 + w * l1);
}

__global__ __launch_bounds__(256) void loss_kernel(
    const float* __restrict__ vlog, const float* __restrict__ plog,
    const float* __restrict__ smean, const float* __restrict__ ret,
    const float* __restrict__ wgt, const int* __restrict__ act,
    const float* __restrict__ scale, float* __restrict__ loss)
{
    __shared__ float sbins[NBc];
    __shared__ float svl[NBc];
    __shared__ float sred[8];
    __shared__ float sres[4];

    int i = blockIdx.x;
    int b = i / TM1, t = i - b * TM1;
    int row = b * Tc + t;
    int tid = threadIdx.x;

    if (tid < NBc) {
        sbins[tid] = bin_val(tid);
        svl[tid] = vlog[(size_t)row * NBc + tid];
    }
    __syncthreads();

    float v = (tid < NBc) ? svl[tid] : -3.4e38f;
    #pragma unroll
    for (int o = 16; o; o >>= 1) v = fmaxf(v, __shfl_xor_sync(0xffffffffu, v, o));
    if ((tid & 31) == 0) sred[tid >> 5] = v;
    __syncthreads();
    if (tid < 32) {
        float m = (tid < 8) ? sred[tid] : -3.4e38f;
        #pragma unroll
        for (int o = 4; o; o >>= 1) m = fmaxf(m, __shfl_xor_sync(0xffffffffu, m, o));
        if (tid == 0) sres[0] = m;
    }
    __syncthreads();
    float M = sres[0];
    float e = (tid < NBc) ? expf(svl[tid] - M) : 0.f;
    #pragma unroll
    for (int o = 16; o; o >>= 1) e += __shfl_xor_sync(0xffffffffu, e, o);
    if ((tid & 31) == 0) sred[tid >> 5] = e;
    __syncthreads();
    if (tid < 32) {
        float s = (tid < 8) ? sred[tid] : 0.f;
        #pragma unroll
        for (int o = 4; o; o >>= 1) s += __shfl_xor_sync(0xffffffffu, s, o);
        if (tid == 0) sres[0] = M + logf(s);
    }
    __syncthreads();
    float logZ = sres[0];

    if (tid < 32) {
        float p0 = plog[(size_t)row * Ac + tid];
        float p1 = plog[(size_t)row * Ac + tid + 32];
        float m = fmaxf(p0, p1);
        #pragma unroll
        for (int o = 16; o; o >>= 1) m = fmaxf(m, __shfl_xor_sync(0xffffffffu, m, o));
        float e0 = expf(p0 - m), e1 = expf(p1 - m);
        float s = e0 + e1;
        #pragma unroll
        for (int o = 16; o; o >>= 1) s += __shfl_xor_sync(0xffffffffu, s, o);
        float inv = 1.0f / s;
        float pr0 = 0.99f * e0 * inv + UNIMIX_A;
        float pr1 = 0.99f * e1 * inv + UNIMIX_A;
        float lp0 = logf(pr0), lp1 = logf(pr1);
        float entp = -(pr0 * lp0 + pr1 * lp1);
        #pragma unroll
        for (int o = 16; o; o >>= 1) entp += __shfl_xor_sync(0xffffffffu, entp, o);
        int a = act[row];
        float lpi = (a == tid) ? lp0 : ((a == tid + 32) ? lp1 : 0.f);
        #pragma unroll
        for (int o = 16; o; o >>= 1) lpi += __shfl_xor_sync(0xffffffffu, lpi, o);
        if (tid == 0) { sres[1] = entp; sres[2] = lpi; }
    }
    __syncthreads();

    if (tid == 0) {
        float reti = ret[i];
        float sm = smean[row];
        float rscale = scale[2];
        float adv = (reti - sm) / rscale;
        float wt = wgt[i];
        float pl = wt * -(sres[2] * adv + ACTENT_C * sres[1]);
        float vl = twohot_nll(svl, sbins, logZ, reti) + twohot_nll(svl, sbins, logZ, sm);
        loss[i] = pl + wt * vl;
    }
}

// ---------------------------------------------------------------------------
// final reduction
// ---------------------------------------------------------------------------
__global__ __launch_bounds__(1024) void reduce_kernel(
    const float* __restrict__ loss, float* __restrict__ out)
{
    __shared__ double sd[32];
    double s = 0.0;
    for (int i = threadIdx.x; i < NLOSS; i += 1024) s += (double)loss[i];
    #pragma unroll
    for (int o = 16; o; o >>= 1) s += __shfl_xor_sync(0xffffffffu, s, o);
    if ((threadIdx.x & 31) == 0) sd[threadIdx.x >> 5] = s;
    __syncthreads();
    if (threadIdx.x == 0) {
        double tot = 0.0;
        #pragma unroll
        for (int w = 0; w < 32; w++) tot += sd[w];
        out[0] = (float)(tot / (double)NLOSS);
    }
}

// ---------------------------------------------------------------------------
// host
// ---------------------------------------------------------------------------
static void run_net_tc(const float* feat, const float* W_in, const float* W_hid,
                       const float* gn, const float* Hw, const float* Hb,
                       float* wtA, float* wtH, int headM, int headTiles,
                       float* h0, float* h1, float* outLogits)
{
    dim3 tb(32, 8);
    transpose_kernel<<<dim3(32, 32), tb>>>(W_in, wtA, Uc);
    for (int i = 0; i < 4; i++)
        transpose_kernel<<<dim3(32, 32), tb>>>(W_hid + (size_t)i * Uc * Uc,
                                               wtA + (size_t)(i + 1) * Uc * Uc, Uc);
    transpose_kernel<<<dim3(32, (headM + 31) / 32), tb>>>(Hw, wtH, headM);

    dim3 gU(NTOK / 128, 8);
    tc_gemm<<<gU, 256, SMEM_B>>>(feat, wtA, nullptr, h0, Uc);
    rmsnorm_silu_kernel<<<NTOK, 256>>>(h0, gn, h0);
    float* cur = h0;
    float* nxt = h1;
    for (int i = 0; i < 4; i++) {
        tc_gemm<<<gU, 256, SMEM_B>>>(cur, wtA + (size_t)(i + 1) * Uc * Uc,
                                     nullptr, nxt, Uc);
        rmsnorm_silu_kernel<<<NTOK, 256>>>(nxt, gn + (size_t)(i + 1) * Uc, nxt);
        float* tmp = cur; cur = nxt; nxt = tmp;
    }
    dim3 gH(NTOK / 128, headTiles);
    tc_gemm<<<gH, 256, SMEM_B>>>(cur, wtH, Hb, outLogits, headM);
}

extern "C" void kernel_launch(void* const* d_in, const int* in_sizes, int n_in,
                              void* d_out, int out_size)
{
    const float* feat   = (const float*)d_in[0];
    const float* reward = (const float*)d_in[1];
    const float* cont   = (const float*)d_in[2];
    const int*   act    = (const int*)  d_in[3];
    const float* pW_in  = (const float*)d_in[4];
    const float* pW_hid = (const float*)d_in[5];
    const float* p_gn   = (const float*)d_in[6];
    const float* pHw    = (const float*)d_in[7];
    const float* pHb    = (const float*)d_in[8];
    const float* vW_in  = (const float*)d_in[9];
    const float* vW_hid = (const float*)d_in[10];
    const float* v_gn   = (const float*)d_in[11];
    const float* vHw    = (const float*)d_in[12];
    const float* vHb    = (const float*)d_in[13];
    const float* sW_in  = (const float*)d_in[14];
    const float* sW_hid = (const float*)d_in[15];
    const float* s_gn   = (const float*)d_in[16];
    const float* sHw    = (const float*)d_in[17];
    const float* sHb    = (const float*)d_in[18];

    float *h0, *h1, *vlog, *slog, *plg, *smean, *ret, *wgt, *scale, *loss;
    float *wtAv, *wtAs, *wtAp, *wtHv, *wtHs, *wtHp;
    cudaGetSymbolAddress((void**)&h0, g_h0);
    cudaGetSymbolAddress((void**)&h1, g_h1);
    cudaGetSymbolAddress((void**)&vlog, g_vlog);
    cudaGetSymbolAddress((void**)&slog, g_slog);
    cudaGetSymbolAddress((void**)&plg, g_plog);
    cudaGetSymbolAddress((void**)&smean, g_smean);
    cudaGetSymbolAddress((void**)&ret, g_ret);
    cudaGetSymbolAddress((void**)&wgt, g_wgt);
    cudaGetSymbolAddress((void**)&scale, g_scale);
    cudaGetSymbolAddress((void**)&loss, g_loss);
    cudaGetSymbolAddress((void**)&wtAv, g_wtA_v);
    cudaGetSymbolAddress((void**)&wtAs, g_wtA_s);
    cudaGetSymbolAddress((void**)&wtAp, g_wtA_p);
    cudaGetSymbolAddress((void**)&wtHv, g_wtH_v);
    cudaGetSymbolAddress((void**)&wtHs, g_wtH_s);
    cudaGetSymbolAddress((void**)&wtHp, g_wtH_p);

    cudaFuncSetAttribute(tc_gemm, cudaFuncAttributeMaxDynamicSharedMemorySize, SMEM_B);
    cudaFuncSetAttribute(percentile_kernel,
                         cudaFuncAttributeMaxDynamicSharedMemorySize, 131072);

    run_net_tc(feat, vW_in, vW_hid, v_gn, vHw, vHb, wtAv, wtHv, NBc, 2, h0, h1, vlog);
    run_net_tc(feat, sW_in, sW_hid, s_gn, sHw, sHb, wtAs, wtHs, NBc, 2, h0, h1, slog);
    slowmean_kernel<<<NTOK, 256>>>(slog, smean);
    run_net_tc(feat, pW_in, pW_hid, p_gn, pHw, pHb, wtAp, wtHp, Ac, 1, h0, h1, plg);

    lamret_kernel<<<1, 64>>>(reward, cont, smean, ret, wgt);
    percentile_kernel<<<1, 1024, 131072>>>(ret, scale);
    loss_kernel<<<NLOSS, 256>>>(vlog, plg, smean, ret, wgt, act, scale, loss);
    reduce_kernel<<<1, 1024>>>(loss, (float*)d_out);
}

// round 4
// speedup vs baseline: 2.7855x; 1.0629x over previous
#include <cuda_runtime.h>
#include <cuda_bf16.h>
#include <math.h>
#include <stdint.h>

// ---------------------------------------------------------------------------
// Problem constants
// ---------------------------------------------------------------------------
#define Bc    64
#define Tc    334
#define Fc    1024
#define Uc    1024
#define Ac    64
#define NBc   255
#define NTOK  (Bc * Tc)        // 21376 = 167 * 128
#define TM1   (Tc - 1)         // 333
#define NLOSS (Bc * TM1)       // 21312
#define LAM_C     0.95f
#define ACTENT_C  3e-4f
#define UNIMIX_A  0.00015625f  // 0.01 / 64
#define NCH   32               // K chunks of 32 (K = 1024)

// smem tile: 128 rows x 32 bf16, row stride 40 bf16 (80 B) -> conflict-free ldmatrix
#define TSTRIDE 40
#define TILE_B  (128 * TSTRIDE * 2)   // 10240 bytes
#define STAGE_B (4 * TILE_B)          // 40960 bytes (Ahi,Alo,Bhi,Blo)
#define NSTAGE  3
#define SMEM_B  (NSTAGE * STAGE_B)    // 122880 bytes

// ---------------------------------------------------------------------------
// Device scratch
// ---------------------------------------------------------------------------
__device__ float g_h0[(size_t)NTOK * Uc];            // fp32 GEMM output
__device__ __nv_bfloat16 g_fhi[(size_t)NTOK * Uc];   // split feat
__device__ __nv_bfloat16 g_flo[(size_t)NTOK * Uc];
__device__ __nv_bfloat16 g_ahi[(size_t)NTOK * Uc];   // split activations
__device__ __nv_bfloat16 g_alo[(size_t)NTOK * Uc];
__device__ float g_vlog[(size_t)NTOK * NBc];
__device__ float g_slog[(size_t)NTOK * NBc];
__device__ float g_plog[(size_t)NTOK * Ac];
__device__ float g_smean[NTOK];
__device__ float g_ret[NLOSS];
__device__ float g_wgt[NLOSS];
__device__ float g_scale[4];
__device__ float g_loss[NLOSS];
// split K-major weights (bf16 hi/lo). Head pad rows never written -> stay 0.
__device__ __nv_bfloat16 g_wv_hi[5ull * 1024 * 1024];
__device__ __nv_bfloat16 g_wv_lo[5ull * 1024 * 1024];
__device__ __nv_bfloat16 g_ws_hi[5ull * 1024 * 1024];
__device__ __nv_bfloat16 g_ws_lo[5ull * 1024 * 1024];
__device__ __nv_bfloat16 g_wp_hi[5ull * 1024 * 1024];
__device__ __nv_bfloat16 g_wp_lo[5ull * 1024 * 1024];
__device__ __nv_bfloat16 g_hv_hi[256 * 1024];
__device__ __nv_bfloat16 g_hv_lo[256 * 1024];
__device__ __nv_bfloat16 g_hs_hi[256 * 1024];
__device__ __nv_bfloat16 g_hs_lo[256 * 1024];
__device__ __nv_bfloat16 g_hp_hi[128 * 1024];
__device__ __nv_bfloat16 g_hp_lo[128 * 1024];

// ---------------------------------------------------------------------------
// helpers
// ---------------------------------------------------------------------------
__device__ __forceinline__ uint32_t smem_u32(const void* p) {
    uint32_t a;
    asm("{ .reg .u64 t; cvta.to.shared.u64 t, %1; cvt.u32.u64 %0, t; }" : "=r"(a) : "l"(p));
    return a;
}
__device__ __forceinline__ void ldm_x4(uint32_t* f, uint32_t addr) {
    asm volatile("ldmatrix.sync.aligned.m8n8.x4.shared.b16 {%0,%1,%2,%3}, [%4];"
                 : "=r"(f[0]), "=r"(f[1]), "=r"(f[2]), "=r"(f[3]) : "r"(addr));
}
__device__ __forceinline__ void mma_bf16(float* c, const uint32_t* a,
                                         uint32_t b0, uint32_t b1) {
    asm volatile(
        "mma.sync.aligned.m16n8k16.row.col.f32.bf16.bf16.f32 "
        "{%0,%1,%2,%3}, {%4,%5,%6,%7}, {%8,%9}, {%0,%1,%2,%3};"
        : "+f"(c[0]), "+f"(c[1]), "+f"(c[2]), "+f"(c[3])
        : "r"(a[0]), "r"(a[1]), "r"(a[2]), "r"(a[3]), "r"(b0), "r"(b1));
}
__device__ __forceinline__ void cp16(uint32_t dst, const void* src) {
    asm volatile("cp.async.ca.shared.global [%0], [%1], 16;" :: "r"(dst), "l"(src));
}
__device__ __forceinline__ void cp_commit() {
    asm volatile("cp.async.commit_group;" ::: "memory");
}
__device__ __forceinline__ void cp_wait2() {
    asm volatile("cp.async.wait_group 2;" ::: "memory");
}

// split fp32 -> hi/lo bf16
__device__ __forceinline__ void split1(float v, __nv_bfloat16& h, __nv_bfloat16& l) {
    h = __float2bfloat16(v);
    l = __float2bfloat16(v - __bfloat162float(h));
}

// ---------------------------------------------------------------------------
// bf16x3-split tensor-core GEMM with cp.async pipeline.
// C[NTOK, Mout] = (Ahi+Alo)[NTOK,1024] @ (Bhi+Blo)[Mpad,1024]^T (+bias)
// ---------------------------------------------------------------------------
__global__ __launch_bounds__(256, 1) void tc_gemm(
    const __nv_bfloat16* __restrict__ Ahi, const __nv_bfloat16* __restrict__ Alo,
    const __nv_bfloat16* __restrict__ Bhi, const __nv_bfloat16* __restrict__ Blo,
    const float* __restrict__ bias, float* __restrict__ C, int Mout)
{
    extern __shared__ char smem[];
    const uint32_t sb = smem_u32(smem);
    const int tid = threadIdx.x;
    const int lane = tid & 31;
    const int warp = tid >> 5;
    const int brow = blockIdx.x * 128;
    const int bcol = blockIdx.y * 128;

    const int m0w = (warp >> 1) * 32;
    const int n0w = (warp & 1) * 64;
    const int lrow = lane & 15;
    const int lcol8 = (lane >> 4) << 3;

    float c[2][8][4];
    #pragma unroll
    for (int i = 0; i < 2; i++)
        #pragma unroll
        for (int j = 0; j < 8; j++)
            #pragma unroll
            for (int q = 0; q < 4; q++) c[i][j][q] = 0.f;

    // cp.async issue: 4 tiles x 512 atoms(16B) per stage; 8 atoms per thread
    auto issue = [&](int stage, int ch) {
        const int k0 = ch * 32;
        #pragma unroll
        for (int j = 0; j < 8; j++) {
            int gid = tid + 256 * j;
            int tl = gid >> 9;           // 0=Ahi 1=Alo 2=Bhi 3=Blo
            int t = gid & 511;
            int r = t >> 2, a = t & 3;
            const __nv_bfloat16* base =
                (tl == 0) ? Ahi : (tl == 1) ? Alo : (tl == 2) ? Bhi : Blo;
            int grow = ((tl < 2) ? brow : bcol) + r;
            const __nv_bfloat16* src = base + (size_t)grow * 1024 + k0 + a * 8;
            uint32_t dst = sb + (uint32_t)stage * STAGE_B + (uint32_t)tl * TILE_B
                         + (uint32_t)(r * 80 + a * 16);
            cp16(dst, src);
        }
        cp_commit();
    };

    issue(0, 0);
    issue(1, 1);
    issue(2, 2);

    for (int ch = 0; ch < NCH; ch++) {
        cp_wait2();
        __syncthreads();

        const uint32_t base = sb + (uint32_t)(ch % NSTAGE) * STAGE_B;
        #pragma unroll
        for (int ss = 0; ss < 2; ss++) {
            const int kk = ss * 16;
            uint32_t aHi[2][4], aLo[2][4];
            #pragma unroll
            for (int i = 0; i < 2; i++) {
                uint32_t ar = base +
                    (uint32_t)((m0w + i * 16 + lrow) * TSTRIDE + kk + lcol8) * 2;
                ldm_x4(aHi[i], ar);
                ldm_x4(aLo[i], ar + TILE_B);
            }
            #pragma unroll
            for (int g = 0; g < 4; g++) {
                uint32_t br = base + 2 * TILE_B +
                    (uint32_t)((n0w + g * 16 + lrow) * TSTRIDE + kk + lcol8) * 2;
                uint32_t bH[4], bL[4];
                ldm_x4(bH, br);
                ldm_x4(bL, br + TILE_B);
                #pragma unroll
                for (int i = 0; i < 2; i++) {
                    mma_bf16(c[i][2 * g],     aHi[i], bH[0], bH[2]);
                    mma_bf16(c[i][2 * g + 1], aHi[i], bH[1], bH[3]);
                    mma_bf16(c[i][2 * g],     aLo[i], bH[0], bH[2]);
                    mma_bf16(c[i][2 * g + 1], aLo[i], bH[1], bH[3]);
                    mma_bf16(c[i][2 * g],     aHi[i], bL[0], bL[2]);
                    mma_bf16(c[i][2 * g + 1], aHi[i], bL[1], bL[3]);
                }
            }
        }
        __syncthreads();
        if (ch + NSTAGE < NCH) issue(ch % NSTAGE, ch + NSTAGE);
        else cp_commit();   // keep one group per iteration
    }

    // epilogue
    const int r = lane >> 2;
    const int cc = 2 * (lane & 3);
    #pragma unroll
    for (int i = 0; i < 2; i++) {
        int rowb = brow + m0w + i * 16;
        #pragma unroll
        for (int j = 0; j < 8; j++) {
            int col = bcol + n0w + j * 8 + cc;
            float b0 = 0.f, b1 = 0.f;
            if (bias) {
                if (col < Mout) b0 = bias[col];
                if (col + 1 < Mout) b1 = bias[col + 1];
            }
            float* p0 = C + (size_t)(rowb + r) * Mout + col;
            float* p1 = C + (size_t)(rowb + r + 8) * Mout + col;
            if (col + 1 < Mout) {
                p0[0] = c[i][j][0] + b0; p0[1] = c[i][j][1] + b1;
                p1[0] = c[i][j][2] + b0; p1[1] = c[i][j][3] + b1;
            } else if (col < Mout) {
                p0[0] = c[i][j][0] + b0;
                p1[0] = c[i][j][2] + b0;
            }
        }
    }
}

// ---------------------------------------------------------------------------
// fused transpose + split: W[1024, M] -> Whi/Wlo[M, 1024] bf16 (K-major)
// ---------------------------------------------------------------------------
__global__ __launch_bounds__(256) void split_wt_kernel(
    const float* __restrict__ W, __nv_bfloat16* __restrict__ Whi,
    __nv_bfloat16* __restrict__ Wlo, int M)
{
    __shared__ float t[32][33];
    int k0 = blockIdx.x * 32, m0 = blockIdx.y * 32;
    int x = threadIdx.x, y = threadIdx.y;   // 32 x 8
    #pragma unroll
    for (int j = 0; j < 32; j += 8) {
        int m = m0 + x;
        if (m < M) t[y + j][x] = W[(size_t)(k0 + y + j) * M + m];
    }
    __syncthreads();
    #pragma unroll
    for (int j = 0; j < 32; j += 8) {
        int m = m0 + y + j;
        if (m < M) {
            float v = t[x][y + j];
            __nv_bfloat16 h, l;
            split1(v, h, l);
            Whi[(size_t)m * 1024 + k0 + x] = h;
            Wlo[(size_t)m * 1024 + k0 + x] = l;
        }
    }
}

// ---------------------------------------------------------------------------
// plain split (feat): fp32 -> hi/lo bf16
// ---------------------------------------------------------------------------
__global__ __launch_bounds__(256) void split_act_kernel(
    const float* __restrict__ X, __nv_bfloat16* __restrict__ Hi,
    __nv_bfloat16* __restrict__ Lo)
{
    size_t i = (size_t)blockIdx.x * 256 + threadIdx.x;   // one float4 per thread
    float4 v = ((const float4*)X)[i];
    __nv_bfloat16 hx, hy, hz, hw, lx, ly, lz, lw;
    split1(v.x, hx, lx); split1(v.y, hy, ly);
    split1(v.z, hz, lz); split1(v.w, hw, lw);
    __nv_bfloat162 h0(hx, hy), h1(hz, hw), l0(lx, ly), l1(lz, lw);
    uint2 hp, lp;
    hp.x = *(uint32_t*)&h0; hp.y = *(uint32_t*)&h1;
    lp.x = *(uint32_t*)&l0; lp.y = *(uint32_t*)&l1;
    ((uint2*)Hi)[i] = hp;
    ((uint2*)Lo)[i] = lp;
}

// ---------------------------------------------------------------------------
// rmsnorm + silu + split -> bf16 hi/lo
// ---------------------------------------------------------------------------
__device__ __forceinline__ float silu_f(float z) { return z / (1.f + expf(-z)); }

__global__ __launch_bounds__(256) void rmsnorm_silu_split_kernel(
    const float* __restrict__ X, const float* __restrict__ g,
    __nv_bfloat16* __restrict__ Hi, __nv_bfloat16* __restrict__ Lo)
{
    int row = blockIdx.x;
    int t = threadIdx.x;
    const float4* x4 = (const float4*)(X + (size_t)row * Uc);
    float4 xv = x4[t];
    float ss = xv.x * xv.x + xv.y * xv.y + xv.z * xv.z + xv.w * xv.w;
    #pragma unroll
    for (int o = 16; o; o >>= 1) ss += __shfl_xor_sync(0xffffffffu, ss, o);
    __shared__ float sh[8];
    if ((t & 31) == 0) sh[t >> 5] = ss;
    __syncthreads();
    if (t < 32) {
        float v = (t < 8) ? sh[t] : 0.f;
        #pragma unroll
        for (int o = 4; o; o >>= 1) v += __shfl_xor_sync(0xffffffffu, v, o);
        if (t == 0) sh[0] = v;
    }
    __syncthreads();
    float r = rsqrtf(sh[0] * (1.0f / (float)Uc) + 1e-6f);
    float4 gv = ((const float4*)g)[t];
    float4 o;
    o.x = silu_f(xv.x * r * gv.x);
    o.y = silu_f(xv.y * r * gv.y);
    o.z = silu_f(xv.z * r * gv.z);
    o.w = silu_f(xv.w * r * gv.w);
    __nv_bfloat16 hx, hy, hz, hw, lx, ly, lz, lw;
    split1(o.x, hx, lx); split1(o.y, hy, ly);
    split1(o.z, hz, lz); split1(o.w, hw, lw);
    __nv_bfloat162 h0(hx, hy), h1(hz, hw), l0(lx, ly), l1(lz, lw);
    uint2 hp, lp;
    hp.x = *(uint32_t*)&h0; hp.y = *(uint32_t*)&h1;
    lp.x = *(uint32_t*)&l0; lp.y = *(uint32_t*)&l1;
    ((uint2*)(Hi + (size_t)row * Uc))[t] = hp;
    ((uint2*)(Lo + (size_t)row * Uc))[t] = lp;
}

// ---------------------------------------------------------------------------
// symexp bins
// ---------------------------------------------------------------------------
__device__ __forceinline__ float bin_val(int i) {
    float u = -20.0f + (40.0f / 254.0f) * (float)i;
    return copysignf(expm1f(fabsf(u)), u);
}

// ---------------------------------------------------------------------------
// slow_mean
// ---------------------------------------------------------------------------
__global__ __launch_bounds__(256) void slowmean_kernel(
    const float* __restrict__ slog, float* __restrict__ smean)
{
    __shared__ float sred[8];
    __shared__ double dden[8], dnum[8];
    int row = blockIdx.x, tid = threadIdx.x;
    float lg = -3.4e38f, bn = 0.f;
    if (tid < NBc) {
        lg = slog[(size_t)row * NBc + tid];
        bn = bin_val(tid);
    }
    float m = lg;
    #pragma unroll
    for (int o = 16; o; o >>= 1) m = fmaxf(m, __shfl_xor_sync(0xffffffffu, m, o));
    if ((tid & 31) == 0) sred[tid >> 5] = m;
    __syncthreads();
    if (tid < 32) {
        float v = (tid < 8) ? sred[tid] : -3.4e38f;
        #pragma unroll
        for (int o = 4; o; o >>= 1) v = fmaxf(v, __shfl_xor_sync(0xffffffffu, v, o));
        if (tid == 0) sred[0] = v;
    }
    __syncthreads();
    float M = sred[0];
    float e = (tid < NBc) ? expf(lg - M) : 0.f;
    double den = (double)e;
    double num = (double)e * (double)bn;
    #pragma unroll
    for (int o = 16; o; o >>= 1) {
        den += __shfl_xor_sync(0xffffffffu, den, o);
        num += __shfl_xor_sync(0xffffffffu, num, o);
    }
    if ((tid & 31) == 0) { dden[tid >> 5] = den; dnum[tid >> 5] = num; }
    __syncthreads();
    if (tid == 0) {
        double D = 0, Nn = 0;
        #pragma unroll
        for (int i = 0; i < 8; i++) { D += dden[i]; Nn += dnum[i]; }
        smean[row] = (float)(Nn / D);
    }
}

// ---------------------------------------------------------------------------
// lambda-return scan
// ---------------------------------------------------------------------------
__global__ void lamret_kernel(
    const float* __restrict__ reward, const float* __restrict__ cont,
    const float* __restrict__ smean, float* __restrict__ ret, float* __restrict__ wgt)
{
    int b = threadIdx.x;
    if (b >= Bc) return;
    float acc = 1.f;
    for (int t = 0; t < TM1; t++) {
        acc *= cont[b * Tc + t];
        wgt[b * TM1 + t] = acc;
    }
    float r = smean[b * Tc + (Tc - 1)];
    for (int t = TM1 - 1; t >= 0; t--) {
        float live = cont[b * Tc + t + 1];
        float interm = reward[b * Tc + t + 1] + (1.f - LAM_C) * live * smean[b * Tc + t + 1];
        r = interm + live * LAM_C * r;
        ret[b * TM1 + t] = r;
    }
}

// ---------------------------------------------------------------------------
// percentile via bitonic sort
// ---------------------------------------------------------------------------
__global__ void percentile_kernel(const float* __restrict__ ret, float* __restrict__ scale)
{
    extern __shared__ float s[];
    const int PAD = 32768;
    for (int i = threadIdx.x; i < PAD; i += blockDim.x)
        s[i] = (i < NLOSS) ? ret[i] : 3.4e38f;
    __syncthreads();
    for (int ksz = 2; ksz <= PAD; ksz <<= 1) {
        for (int j = ksz >> 1; j > 0; j >>= 1) {
            for (int a = threadIdx.x; a < PAD; a += blockDim.x) {
                int p = a ^ j;
                if (p > a) {
                    bool asc = ((a & ksz) == 0);
                    float x = s[a], y = s[p];
                    if ((x > y) == asc) { s[a] = y; s[p] = x; }
                }
            }
            __syncthreads();
        }
    }
    if (threadIdx.x == 0) {
        double p5 = 0.05 * (double)(NLOSS - 1);
        double p95 = 0.95 * (double)(NLOSS - 1);
        int i5 = (int)p5, i95 = (int)p95;
        float f5 = (float)(p5 - i5), f95 = (float)(p95 - i95);
        float lo = s[i5] + f5 * (s[i5 + 1] - s[i5]);
        float hi = s[i95] + f95 * (s[i95 + 1] - s[i95]);
        scale[0] = lo;
        scale[1] = hi;
        scale[2] = fmaxf(hi - lo, 1.0f);
    }
}

// ---------------------------------------------------------------------------
// per-token loss
// ---------------------------------------------------------------------------
__device__ __forceinline__ float twohot_nll(const float* svl, const float* sbins,
                                            float logZ, float y)
{
    y = fminf(fmaxf(y, sbins[0]), sbins[NBc - 1]);
    int lo = 0, hi = NBc - 1;
    while (hi > lo) {
        int mid = (lo + hi) >> 1;
        if (sbins[mid] >= y) hi = mid; else lo = mid + 1;
    }
    int k = hi - 1;
    if (k < 0) k = 0;
    if (k > NBc - 2) k = NBc - 2;
    float bl = sbins[k], bh = sbins[k + 1];
    float w = (y - bl) / (bh - bl);
    w = fminf(fmaxf(w, 0.f), 1.f);
    float l0 = svl[k] - logZ, l1 = svl[k + 1] - logZ;
    return -((1.f - w) * l0 + w * l1);
}

__global__ __launch_bounds__(256) void loss_kernel(
    const float* __restrict__ vlog, const float* __restrict__ plog,
    const float* __restrict__ smean, const float* __restrict__ ret,
    const float* __restrict__ wgt, const int* __restrict__ act,
    const float* __restrict__ scale, float* __restrict__ loss)
{
    __shared__ float sbins[NBc];
    __shared__ float svl[NBc];
    __shared__ float sred[8];
    __shared__ float sres[4];

    int i = blockIdx.x;
    int b = i / TM1, t = i - b * TM1;
    int row = b * Tc + t;
    int tid = threadIdx.x;

    if (tid < NBc) {
        sbins[tid] = bin_val(tid);
        svl[tid] = vlog[(size_t)row * NBc + tid];
    }
    __syncthreads();

    float v = (tid < NBc) ? svl[tid] : -3.4e38f;
    #pragma unroll
    for (int o = 16; o; o >>= 1) v = fmaxf(v, __shfl_xor_sync(0xffffffffu, v, o));
    if ((tid & 31) == 0) sred[tid >> 5] = v;
    __syncthreads();
    if (tid < 32) {
        float m = (tid < 8) ? sred[tid] : -3.4e38f;
        #pragma unroll
        for (int o = 4; o; o >>= 1) m = fmaxf(m, __shfl_xor_sync(0xffffffffu, m, o));
        if (tid == 0) sres[0] = m;
    }
    __syncthreads();
    float M = sres[0];
    float e = (tid < NBc) ? expf(svl[tid] - M) : 0.f;
    #pragma unroll
    for (int o = 16; o; o >>= 1) e += __shfl_xor_sync(0xffffffffu, e, o);
    if ((tid & 31) == 0) sred[tid >> 5] = e;
    __syncthreads();
    if (tid < 32) {
        float s = (tid < 8) ? sred[tid] : 0.f;
        #pragma unroll
        for (int o = 4; o; o >>= 1) s += __shfl_xor_sync(0xffffffffu, s, o);
        if (tid == 0) sres[0] = M + logf(s);
    }
    __syncthreads();
    float logZ = sres[0];

    if (tid < 32) {
        float p0 = plog[(size_t)row * Ac + tid];
        float p1 = plog[(size_t)row * Ac + tid + 32];
        float m = fmaxf(p0, p1);
        #pragma unroll
        for (int o = 16; o; o >>= 1) m = fmaxf(m, __shfl_xor_sync(0xffffffffu, m, o));
        float e0 = expf(p0 - m), e1 = expf(p1 - m);
        float s = e0 + e1;
        #pragma unroll
        for (int o = 16; o; o >>= 1) s += __shfl_xor_sync(0xffffffffu, s, o);
        float inv = 1.0f / s;
        float pr0 = 0.99f * e0 * inv + UNIMIX_A;
        float pr1 = 0.99f * e1 * inv + UNIMIX_A;
        float lp0 = logf(pr0), lp1 = logf(pr1);
        float entp = -(pr0 * lp0 + pr1 * lp1);
        #pragma unroll
        for (int o = 16; o; o >>= 1) entp += __shfl_xor_sync(0xffffffffu, entp, o);
        int a = act[row];
        float lpi = (a == tid) ? lp0 : ((a == tid + 32) ? lp1 : 0.f);
        #pragma unroll
        for (int o = 16; o; o >>= 1) lpi += __shfl_xor_sync(0xffffffffu, lpi, o);
        if (tid == 0) { sres[1] = entp; sres[2] = lpi; }
    }
    __syncthreads();

    if (tid == 0) {
        float reti = ret[i];
        float sm = smean[row];
        float rscale = scale[2];
        float adv = (reti - sm) / rscale;
        float wt = wgt[i];
        float pl = wt * -(sres[2] * adv + ACTENT_C * sres[1]);
        float vl = twohot_nll(svl, sbins, logZ, reti) + twohot_nll(svl, sbins, logZ, sm);
        loss[i] = pl + wt * vl;
    }
}

// ---------------------------------------------------------------------------
// final reduction
// ---------------------------------------------------------------------------
__global__ __launch_bounds__(1024) void reduce_kernel(
    const float* __restrict__ loss, float* __restrict__ out)
{
    __shared__ double sd[32];
    double s = 0.0;
    for (int i = threadIdx.x; i < NLOSS; i += 1024) s += (double)loss[i];
    #pragma unroll
    for (int o = 16; o; o >>= 1) s += __shfl_xor_sync(0xffffffffu, s, o);
    if ((threadIdx.x & 31) == 0) sd[threadIdx.x >> 5] = s;
    __syncthreads();
    if (threadIdx.x == 0) {
        double tot = 0.0;
        #pragma unroll
        for (int w = 0; w < 32; w++) tot += sd[w];
        out[0] = (float)(tot / (double)NLOSS);
    }
}

// ---------------------------------------------------------------------------
// host
// ---------------------------------------------------------------------------
struct NetBufs {
    __nv_bfloat16 *whi, *wlo;   // 5 x 1024 x 1024
    __nv_bfloat16 *hhi, *hlo;   // head, padded rows
};

static void run_net(const float* W_in, const float* W_hid, const float* gn,
                    const float* Hw, const float* Hb, const NetBufs& nb,
                    int headM, int headTiles,
                    const __nv_bfloat16* fhi, const __nv_bfloat16* flo,
                    float* h0, __nv_bfloat16* ahi, __nv_bfloat16* alo,
                    float* outLogits)
{
    dim3 tb(32, 8);
    split_wt_kernel<<<dim3(32, 32), tb>>>(W_in, nb.whi, nb.wlo, Uc);
    for (int i = 0; i < 4; i++)
        split_wt_kernel<<<dim3(32, 32), tb>>>(
            W_hid + (size_t)i * Uc * Uc,
            nb.whi + (size_t)(i + 1) * Uc * Uc,
            nb.wlo + (size_t)(i + 1) * Uc * Uc, Uc);
    split_wt_kernel<<<dim3(32, (headM + 31) / 32), tb>>>(Hw, nb.hhi, nb.hlo, headM);

    dim3 gU(NTOK / 128, 8);
    tc_gemm<<<gU, 256, SMEM_B>>>(fhi, flo, nb.whi, nb.wlo, nullptr, h0, Uc);
    rmsnorm_silu_split_kernel<<<NTOK, 256>>>(h0, gn, ahi, alo);
    for (int i = 0; i < 4; i++) {
        tc_gemm<<<gU, 256, SMEM_B>>>(ahi, alo,
                                     nb.whi + (size_t)(i + 1) * Uc * Uc,
                                     nb.wlo + (size_t)(i + 1) * Uc * Uc,
                                     nullptr, h0, Uc);
        rmsnorm_silu_split_kernel<<<NTOK, 256>>>(h0, gn + (size_t)(i + 1) * Uc, ahi, alo);
    }
    dim3 gH(NTOK / 128, headTiles);
    tc_gemm<<<gH, 256, SMEM_B>>>(ahi, alo, nb.hhi, nb.hlo, Hb, outLogits, headM);
}

extern "C" void kernel_launch(void* const* d_in, const int* in_sizes, int n_in,
                              void* d_out, int out_size)
{
    const float* feat   = (const float*)d_in[0];
    const float* reward = (const float*)d_in[1];
    const float* cont   = (const float*)d_in[2];
    const int*   act    = (const int*)  d_in[3];
    const float* pW_in  = (const float*)d_in[4];
    const float* pW_hid = (const float*)d_in[5];
    const float* p_gn   = (const float*)d_in[6];
    const float* pHw    = (const float*)d_in[7];
    const float* pHb    = (const float*)d_in[8];
    const float* vW_in  = (const float*)d_in[9];
    const float* vW_hid = (const float*)d_in[10];
    const float* v_gn   = (const float*)d_in[11];
    const float* vHw    = (const float*)d_in[12];
    const float* vHb    = (const float*)d_in[13];
    const float* sW_in  = (const float*)d_in[14];
    const float* sW_hid = (const float*)d_in[15];
    const float* s_gn   = (const float*)d_in[16];
    const float* sHw    = (const float*)d_in[17];
    const float* sHb    = (const float*)d_in[18];

    float *h0, *vlog, *slog, *plg, *smean, *ret, *wgt, *scale, *loss;
    __nv_bfloat16 *fhi, *flo, *ahi, *alo;
    NetBufs nbv, nbs, nbp;
    cudaGetSymbolAddress((void**)&h0, g_h0);
    cudaGetSymbolAddress((void**)&fhi, g_fhi);
    cudaGetSymbolAddress((void**)&flo, g_flo);
    cudaGetSymbolAddress((void**)&ahi, g_ahi);
    cudaGetSymbolAddress((void**)&alo, g_alo);
    cudaGetSymbolAddress((void**)&vlog, g_vlog);
    cudaGetSymbolAddress((void**)&slog, g_slog);
    cudaGetSymbolAddress((void**)&plg, g_plog);
    cudaGetSymbolAddress((void**)&smean, g_smean);
    cudaGetSymbolAddress((void**)&ret, g_ret);
    cudaGetSymbolAddress((void**)&wgt, g_wgt);
    cudaGetSymbolAddress((void**)&scale, g_scale);
    cudaGetSymbolAddress((void**)&loss, g_loss);
    cudaGetSymbolAddress((void**)&nbv.whi, g_wv_hi);
    cudaGetSymbolAddress((void**)&nbv.wlo, g_wv_lo);
    cudaGetSymbolAddress((void**)&nbs.whi, g_ws_hi);
    cudaGetSymbolAddress((void**)&nbs.wlo, g_ws_lo);
    cudaGetSymbolAddress((void**)&nbp.whi, g_wp_hi);
    cudaGetSymbolAddress((void**)&nbp.wlo, g_wp_lo);
    cudaGetSymbolAddress((void**)&nbv.hhi, g_hv_hi);
    cudaGetSymbolAddress((void**)&nbv.hlo, g_hv_lo);
    cudaGetSymbolAddress((void**)&nbs.hhi, g_hs_hi);
    cudaGetSymbolAddress((void**)&nbs.hlo, g_hs_lo);
    cudaGetSymbolAddress((void**)&nbp.hhi, g_hp_hi);
    cudaGetSymbolAddress((void**)&nbp.hlo, g_hp_lo);

    cudaFuncSetAttribute(tc_gemm, cudaFuncAttributeMaxDynamicSharedMemorySize, SMEM_B);
    cudaFuncSetAttribute(percentile_kernel,
                         cudaFuncAttributeMaxDynamicSharedMemorySize, 131072);

    split_act_kernel<<<NTOK, 256>>>(feat, fhi, flo);

    run_net(vW_in, vW_hid, v_gn, vHw, vHb, nbv, NBc, 2, fhi, flo, h0, ahi, alo, vlog);
    run_net(sW_in, sW_hid, s_gn, sHw, sHb, nbs, NBc, 2, fhi, flo, h0, ahi, alo, slog);
    slowmean_kernel<<<NTOK, 256>>>(slog, smean);
    run_net(pW_in, pW_hid, p_gn, pHw, pHb, nbp, Ac, 1, fhi, flo, h0, ahi, alo, plg);

    lamret_kernel<<<1, 64>>>(reward, cont, smean, ret, wgt);
    percentile_kernel<<<1, 1024, 131072>>>(ret, scale);
    loss_kernel<<<NLOSS, 256>>>(vlog, plg, smean, ret, wgt, act, scale, loss);
    reduce_kernel<<<1, 1024>>>(loss, (float*)d_out);
}

// round 5
// speedup vs baseline: 2.9447x; 1.0572x over previous
#include <cuda_runtime.h>
#include <cuda_bf16.h>
#include <math.h>
#include <stdint.h>

// ---------------------------------------------------------------------------
// Problem constants
// ---------------------------------------------------------------------------
#define Bc    64
#define Tc    334
#define Fc    1024
#define Uc    1024
#define Ac    64
#define NBc   255
#define NTOK  (Bc * Tc)        // 21376 = 167 * 128
#define TM1   (Tc - 1)         // 333
#define NLOSS (Bc * TM1)       // 21312
#define LAM_C     0.95f
#define ACTENT_C  3e-4f
#define UNIMIX_A  0.00015625f  // 0.01 / 64
#define NCH   32               // K chunks of 32 (K = 1024)

// smem tile: 128 rows x 32 bf16, row stride 40 bf16 (80 B) -> conflict-free ldmatrix
#define TSTRIDE 40
#define TILE_B  (128 * TSTRIDE * 2)   // 10240 bytes
#define STAGE_B (4 * TILE_B)          // 40960 bytes (Ahi,Alo,Bhi,Blo)
#define NSTAGE  2
#define SMEM_B  (NSTAGE * STAGE_B)    // 81920 bytes -> 2 CTAs/SM

// ---------------------------------------------------------------------------
// Device scratch
// ---------------------------------------------------------------------------
__device__ float g_h0[(size_t)NTOK * Uc];            // fp32 GEMM output
__device__ __nv_bfloat16 g_fhi[(size_t)NTOK * Uc];   // split feat
__device__ __nv_bfloat16 g_flo[(size_t)NTOK * Uc];
__device__ __nv_bfloat16 g_ahi[(size_t)NTOK * Uc];   // split activations
__device__ __nv_bfloat16 g_alo[(size_t)NTOK * Uc];
__device__ float g_vlog[(size_t)NTOK * NBc];
__device__ float g_slog[(size_t)NTOK * NBc];
__device__ float g_plog[(size_t)NTOK * Ac];
__device__ float g_smean[NTOK];
__device__ float g_ret[NLOSS];
__device__ float g_wgt[NLOSS];
__device__ float g_scale[4];
__device__ float g_loss[NLOSS];
// split K-major weights (bf16 hi/lo). Head pad rows never written -> stay 0.
__device__ __nv_bfloat16 g_wv_hi[5ull * 1024 * 1024];
__device__ __nv_bfloat16 g_wv_lo[5ull * 1024 * 1024];
__device__ __nv_bfloat16 g_ws_hi[5ull * 1024 * 1024];
__device__ __nv_bfloat16 g_ws_lo[5ull * 1024 * 1024];
__device__ __nv_bfloat16 g_wp_hi[5ull * 1024 * 1024];
__device__ __nv_bfloat16 g_wp_lo[5ull * 1024 * 1024];
__device__ __nv_bfloat16 g_hv_hi[256 * 1024];
__device__ __nv_bfloat16 g_hv_lo[256 * 1024];
__device__ __nv_bfloat16 g_hs_hi[256 * 1024];
__device__ __nv_bfloat16 g_hs_lo[256 * 1024];
__device__ __nv_bfloat16 g_hp_hi[128 * 1024];
__device__ __nv_bfloat16 g_hp_lo[128 * 1024];

// ---------------------------------------------------------------------------
// helpers
// ---------------------------------------------------------------------------
__device__ __forceinline__ uint32_t smem_u32(const void* p) {
    uint32_t a;
    asm("{ .reg .u64 t; cvta.to.shared.u64 t, %1; cvt.u32.u64 %0, t; }" : "=r"(a) : "l"(p));
    return a;
}
__device__ __forceinline__ void ldm_x4(uint32_t* f, uint32_t addr) {
    asm volatile("ldmatrix.sync.aligned.m8n8.x4.shared.b16 {%0,%1,%2,%3}, [%4];"
                 : "=r"(f[0]), "=r"(f[1]), "=r"(f[2]), "=r"(f[3]) : "r"(addr));
}
__device__ __forceinline__ void mma_bf16(float* c, const uint32_t* a,
                                         uint32_t b0, uint32_t b1) {
    asm volatile(
        "mma.sync.aligned.m16n8k16.row.col.f32.bf16.bf16.f32 "
        "{%0,%1,%2,%3}, {%4,%5,%6,%7}, {%8,%9}, {%0,%1,%2,%3};"
        : "+f"(c[0]), "+f"(c[1]), "+f"(c[2]), "+f"(c[3])
        : "r"(a[0]), "r"(a[1]), "r"(a[2]), "r"(a[3]), "r"(b0), "r"(b1));
}
__device__ __forceinline__ void cp16(uint32_t dst, const void* src) {
    asm volatile("cp.async.ca.shared.global [%0], [%1], 16;" :: "r"(dst), "l"(src));
}
__device__ __forceinline__ void cp_commit() {
    asm volatile("cp.async.commit_group;" ::: "memory");
}
__device__ __forceinline__ void cp_wait1() {
    asm volatile("cp.async.wait_group 1;" ::: "memory");
}

// split fp32 -> hi/lo bf16
__device__ __forceinline__ void split1(float v, __nv_bfloat16& h, __nv_bfloat16& l) {
    h = __float2bfloat16(v);
    l = __float2bfloat16(v - __bfloat162float(h));
}

// ---------------------------------------------------------------------------
// bf16x3-split tensor-core GEMM with cp.async 2-stage pipeline, 2 CTAs/SM.
// C[NTOK, Mout] = (Ahi+Alo)[NTOK,1024] @ (Bhi+Blo)[Mpad,1024]^T (+bias)
// ---------------------------------------------------------------------------
__global__ __launch_bounds__(256, 2) void tc_gemm(
    const __nv_bfloat16* __restrict__ Ahi, const __nv_bfloat16* __restrict__ Alo,
    const __nv_bfloat16* __restrict__ Bhi, const __nv_bfloat16* __restrict__ Blo,
    const float* __restrict__ bias, float* __restrict__ C, int Mout)
{
    extern __shared__ char smem[];
    const uint32_t sb = smem_u32(smem);
    const int tid = threadIdx.x;
    const int lane = tid & 31;
    const int warp = tid >> 5;
    const int brow = blockIdx.x * 128;
    const int bcol = blockIdx.y * 128;

    const int m0w = (warp >> 1) * 32;
    const int n0w = (warp & 1) * 64;
    const int lrow = lane & 15;
    const int lcol8 = (lane >> 4) << 3;

    float c[2][8][4];
    #pragma unroll
    for (int i = 0; i < 2; i++)
        #pragma unroll
        for (int j = 0; j < 8; j++)
            #pragma unroll
            for (int q = 0; q < 4; q++) c[i][j][q] = 0.f;

    // cp.async issue: 4 tiles x 512 atoms(16B) per stage; 8 atoms per thread
    auto issue = [&](int stage, int ch) {
        const int k0 = ch * 32;
        #pragma unroll
        for (int j = 0; j < 8; j++) {
            int gid = tid + 256 * j;
            int tl = gid >> 9;           // 0=Ahi 1=Alo 2=Bhi 3=Blo
            int t = gid & 511;
            int r = t >> 2, a = t & 3;
            const __nv_bfloat16* base =
                (tl == 0) ? Ahi : (tl == 1) ? Alo : (tl == 2) ? Bhi : Blo;
            int grow = ((tl < 2) ? brow : bcol) + r;
            const __nv_bfloat16* src = base + (size_t)grow * 1024 + k0 + a * 8;
            uint32_t dst = sb + (uint32_t)stage * STAGE_B + (uint32_t)tl * TILE_B
                         + (uint32_t)(r * 80 + a * 16);
            cp16(dst, src);
        }
        cp_commit();
    };

    issue(0, 0);
    issue(1, 1);

    for (int ch = 0; ch < NCH; ch++) {
        cp_wait1();
        __syncthreads();

        const uint32_t base = sb + (uint32_t)(ch & 1) * STAGE_B;
        #pragma unroll
        for (int ss = 0; ss < 2; ss++) {
            const int kk = ss * 16;
            uint32_t aHi[2][4], aLo[2][4], bH[4][4];
            #pragma unroll
            for (int i = 0; i < 2; i++) {
                uint32_t ar = base +
                    (uint32_t)((m0w + i * 16 + lrow) * TSTRIDE + kk + lcol8) * 2;
                ldm_x4(aHi[i], ar);
                ldm_x4(aLo[i], ar + TILE_B);
            }
            #pragma unroll
            for (int g = 0; g < 4; g++) {
                uint32_t br = base + 2 * TILE_B +
                    (uint32_t)((n0w + g * 16 + lrow) * TSTRIDE + kk + lcol8) * 2;
                ldm_x4(bH[g], br);
            }
            // pass 1: Ahi x Bhi (16 independent MMAs)
            #pragma unroll
            for (int g = 0; g < 4; g++)
                #pragma unroll
                for (int i = 0; i < 2; i++) {
                    mma_bf16(c[i][2 * g],     aHi[i], bH[g][0], bH[g][2]);
                    mma_bf16(c[i][2 * g + 1], aHi[i], bH[g][1], bH[g][3]);
                }
            // pass 2: Alo x Bhi
            #pragma unroll
            for (int g = 0; g < 4; g++)
                #pragma unroll
                for (int i = 0; i < 2; i++) {
                    mma_bf16(c[i][2 * g],     aLo[i], bH[g][0], bH[g][2]);
                    mma_bf16(c[i][2 * g + 1], aLo[i], bH[g][1], bH[g][3]);
                }
            // pass 3: Ahi x Blo (bL loaded just-in-time, reuses 4 regs)
            #pragma unroll
            for (int g = 0; g < 4; g++) {
                uint32_t bL[4];
                uint32_t br = base + 3 * TILE_B +
                    (uint32_t)((n0w + g * 16 + lrow) * TSTRIDE + kk + lcol8) * 2;
                ldm_x4(bL, br);
                #pragma unroll
                for (int i = 0; i < 2; i++) {
                    mma_bf16(c[i][2 * g],     aHi[i], bL[0], bL[2]);
                    mma_bf16(c[i][2 * g + 1], aHi[i], bL[1], bL[3]);
                }
            }
        }
        __syncthreads();
        if (ch + NSTAGE < NCH) issue(ch & 1, ch + NSTAGE);
        else cp_commit();   // keep one group per iteration
    }

    // epilogue
    const int r = lane >> 2;
    const int cc = 2 * (lane & 3);
    #pragma unroll
    for (int i = 0; i < 2; i++) {
        int rowb = brow + m0w + i * 16;
        #pragma unroll
        for (int j = 0; j < 8; j++) {
            int col = bcol + n0w + j * 8 + cc;
            float b0 = 0.f, b1 = 0.f;
            if (bias) {
                if (col < Mout) b0 = bias[col];
                if (col + 1 < Mout) b1 = bias[col + 1];
            }
            float* p0 = C + (size_t)(rowb + r) * Mout + col;
            float* p1 = C + (size_t)(rowb + r + 8) * Mout + col;
            if (col + 1 < Mout) {
                p0[0] = c[i][j][0] + b0; p0[1] = c[i][j][1] + b1;
                p1[0] = c[i][j][2] + b0; p1[1] = c[i][j][3] + b1;
            } else if (col < Mout) {
                p0[0] = c[i][j][0] + b0;
                p1[0] = c[i][j][2] + b0;
            }
        }
    }
}

// ---------------------------------------------------------------------------
// batched transpose + split for the 5 square matrices of one net
// z = 0 -> W_in, z >= 1 -> W_hid[z-1]; all [1024,1024]
// ---------------------------------------------------------------------------
__global__ __launch_bounds__(256) void split_wt5_kernel(
    const float* __restrict__ W_in, const float* __restrict__ W_hid,
    __nv_bfloat16* __restrict__ Whi, __nv_bfloat16* __restrict__ Wlo)
{
    __shared__ float t[32][33];
    int z = blockIdx.z;
    const float* W = (z == 0) ? W_in : (W_hid + (size_t)(z - 1) * Uc * Uc);
    __nv_bfloat16* dhi = Whi + (size_t)z * Uc * Uc;
    __nv_bfloat16* dlo = Wlo + (size_t)z * Uc * Uc;
    int k0 = blockIdx.x * 32, m0 = blockIdx.y * 32;
    int x = threadIdx.x, y = threadIdx.y;   // 32 x 8
    #pragma unroll
    for (int j = 0; j < 32; j += 8)
        t[y + j][x] = W[(size_t)(k0 + y + j) * Uc + m0 + x];
    __syncthreads();
    #pragma unroll
    for (int j = 0; j < 32; j += 8) {
        int m = m0 + y + j;
        float v = t[x][y + j];
        __nv_bfloat16 h, l;
        split1(v, h, l);
        dhi[(size_t)m * 1024 + k0 + x] = h;
        dlo[(size_t)m * 1024 + k0 + x] = l;
    }
}

// head transpose + split: W[1024, M] -> [M,1024]
__global__ __launch_bounds__(256) void split_wt_kernel(
    const float* __restrict__ W, __nv_bfloat16* __restrict__ Whi,
    __nv_bfloat16* __restrict__ Wlo, int M)
{
    __shared__ float t[32][33];
    int k0 = blockIdx.x * 32, m0 = blockIdx.y * 32;
    int x = threadIdx.x, y = threadIdx.y;   // 32 x 8
    #pragma unroll
    for (int j = 0; j < 32; j += 8) {
        int m = m0 + x;
        if (m < M) t[y + j][x] = W[(size_t)(k0 + y + j) * M + m];
    }
    __syncthreads();
    #pragma unroll
    for (int j = 0; j < 32; j += 8) {
        int m = m0 + y + j;
        if (m < M) {
            float v = t[x][y + j];
            __nv_bfloat16 h, l;
            split1(v, h, l);
            Whi[(size_t)m * 1024 + k0 + x] = h;
            Wlo[(size_t)m * 1024 + k0 + x] = l;
        }
    }
}

// ---------------------------------------------------------------------------
// plain split (feat): fp32 -> hi/lo bf16
// ---------------------------------------------------------------------------
__global__ __launch_bounds__(256) void split_act_kernel(
    const float* __restrict__ X, __nv_bfloat16* __restrict__ Hi,
    __nv_bfloat16* __restrict__ Lo)
{
    size_t i = (size_t)blockIdx.x * 256 + threadIdx.x;   // one float4 per thread
    float4 v = ((const float4*)X)[i];
    __nv_bfloat16 hx, hy, hz, hw, lx, ly, lz, lw;
    split1(v.x, hx, lx); split1(v.y, hy, ly);
    split1(v.z, hz, lz); split1(v.w, hw, lw);
    __nv_bfloat162 h0(hx, hy), h1(hz, hw), l0(lx, ly), l1(lz, lw);
    uint2 hp, lp;
    hp.x = *(uint32_t*)&h0; hp.y = *(uint32_t*)&h1;
    lp.x = *(uint32_t*)&l0; lp.y = *(uint32_t*)&l1;
    ((uint2*)Hi)[i] = hp;
    ((uint2*)Lo)[i] = lp;
}

// ---------------------------------------------------------------------------
// rmsnorm + silu + split -> bf16 hi/lo
// ---------------------------------------------------------------------------
__device__ __forceinline__ float silu_f(float z) { return z / (1.f + expf(-z)); }

__global__ __launch_bounds__(256) void rmsnorm_silu_split_kernel(
    const float* __restrict__ X, const float* __restrict__ g,
    __nv_bfloat16* __restrict__ Hi, __nv_bfloat16* __restrict__ Lo)
{
    int row = blockIdx.x;
    int t = threadIdx.x;
    const float4* x4 = (const float4*)(X + (size_t)row * Uc);
    float4 xv = x4[t];
    float ss = xv.x * xv.x + xv.y * xv.y + xv.z * xv.z + xv.w * xv.w;
    #pragma unroll
    for (int o = 16; o; o >>= 1) ss += __shfl_xor_sync(0xffffffffu, ss, o);
    __shared__ float sh[8];
    if ((t & 31) == 0) sh[t >> 5] = ss;
    __syncthreads();
    if (t < 32) {
        float v = (t < 8) ? sh[t] : 0.f;
        #pragma unroll
        for (int o = 4; o; o >>= 1) v += __shfl_xor_sync(0xffffffffu, v, o);
        if (t == 0) sh[0] = v;
    }
    __syncthreads();
    float r = rsqrtf(sh[0] * (1.0f / (float)Uc) + 1e-6f);
    float4 gv = ((const float4*)g)[t];
    float4 o;
    o.x = silu_f(xv.x * r * gv.x);
    o.y = silu_f(xv.y * r * gv.y);
    o.z = silu_f(xv.z * r * gv.z);
    o.w = silu_f(xv.w * r * gv.w);
    __nv_bfloat16 hx, hy, hz, hw, lx, ly, lz, lw;
    split1(o.x, hx, lx); split1(o.y, hy, ly);
    split1(o.z, hz, lz); split1(o.w, hw, lw);
    __nv_bfloat162 h0(hx, hy), h1(hz, hw), l0(lx, ly), l1(lz, lw);
    uint2 hp, lp;
    hp.x = *(uint32_t*)&h0; hp.y = *(uint32_t*)&h1;
    lp.x = *(uint32_t*)&l0; lp.y = *(uint32_t*)&l1;
    ((uint2*)(Hi + (size_t)row * Uc))[t] = hp;
    ((uint2*)(Lo + (size_t)row * Uc))[t] = lp;
}

// ---------------------------------------------------------------------------
// symexp bins
// ---------------------------------------------------------------------------
__device__ __forceinline__ float bin_val(int i) {
    float u = -20.0f + (40.0f / 254.0f) * (float)i;
    return copysignf(expm1f(fabsf(u)), u);
}

// ---------------------------------------------------------------------------
// slow_mean
// ---------------------------------------------------------------------------
__global__ __launch_bounds__(256) void slowmean_kernel(
    const float* __restrict__ slog, float* __restrict__ smean)
{
    __shared__ float sred[8];
    __shared__ double dden[8], dnum[8];
    int row = blockIdx.x, tid = threadIdx.x;
    float lg = -3.4e38f, bn = 0.f;
    if (tid < NBc) {
        lg = slog[(size_t)row * NBc + tid];
        bn = bin_val(tid);
    }
    float m = lg;
    #pragma unroll
    for (int o = 16; o; o >>= 1) m = fmaxf(m, __shfl_xor_sync(0xffffffffu, m, o));
    if ((tid & 31) == 0) sred[tid >> 5] = m;
    __syncthreads();
    if (tid < 32) {
        float v = (tid < 8) ? sred[tid] : -3.4e38f;
        #pragma unroll
        for (int o = 4; o; o >>= 1) v = fmaxf(v, __shfl_xor_sync(0xffffffffu, v, o));
        if (tid == 0) sred[0] = v;
    }
    __syncthreads();
    float M = sred[0];
    float e = (tid < NBc) ? expf(lg - M) : 0.f;
    double den = (double)e;
    double num = (double)e * (double)bn;
    #pragma unroll
    for (int o = 16; o; o >>= 1) {
        den += __shfl_xor_sync(0xffffffffu, den, o);
        num += __shfl_xor_sync(0xffffffffu, num, o);
    }
    if ((tid & 31) == 0) { dden[tid >> 5] = den; dnum[tid >> 5] = num; }
    __syncthreads();
    if (tid == 0) {
        double D = 0, Nn = 0;
        #pragma unroll
        for (int i = 0; i < 8; i++) { D += dden[i]; Nn += dnum[i]; }
        smean[row] = (float)(Nn / D);
    }
}

// ---------------------------------------------------------------------------
// lambda-return scan
// ---------------------------------------------------------------------------
__global__ void lamret_kernel(
    const float* __restrict__ reward, const float* __restrict__ cont,
    const float* __restrict__ smean, float* __restrict__ ret, float* __restrict__ wgt)
{
    int b = threadIdx.x;
    if (b >= Bc) return;
    float acc = 1.f;
    for (int t = 0; t < TM1; t++) {
        acc *= cont[b * Tc + t];
        wgt[b * TM1 + t] = acc;
    }
    float r = smean[b * Tc + (Tc - 1)];
    for (int t = TM1 - 1; t >= 0; t--) {
        float live = cont[b * Tc + t + 1];
        float interm = reward[b * Tc + t + 1] + (1.f - LAM_C) * live * smean[b * Tc + t + 1];
        r = interm + live * LAM_C * r;
        ret[b * TM1 + t] = r;
    }
}

// ---------------------------------------------------------------------------
// percentile via bitonic sort
// ---------------------------------------------------------------------------
__global__ void percentile_kernel(const float* __restrict__ ret, float* __restrict__ scale)
{
    extern __shared__ float s[];
    const int PAD = 32768;
    for (int i = threadIdx.x; i < PAD; i += blockDim.x)
        s[i] = (i < NLOSS) ? ret[i] : 3.4e38f;
    __syncthreads();
    for (int ksz = 2; ksz <= PAD; ksz <<= 1) {
        for (int j = ksz >> 1; j > 0; j >>= 1) {
            for (int a = threadIdx.x; a < PAD; a += blockDim.x) {
                int p = a ^ j;
                if (p > a) {
                    bool asc = ((a & ksz) == 0);
                    float x = s[a], y = s[p];
                    if ((x > y) == asc) { s[a] = y; s[p] = x; }
                }
            }
            __syncthreads();
        }
    }
    if (threadIdx.x == 0) {
        double p5 = 0.05 * (double)(NLOSS - 1);
        double p95 = 0.95 * (double)(NLOSS - 1);
        int i5 = (int)p5, i95 = (int)p95;
        float f5 = (float)(p5 - i5), f95 = (float)(p95 - i95);
        float lo = s[i5] + f5 * (s[i5 + 1] - s[i5]);
        float hi = s[i95] + f95 * (s[i95 + 1] - s[i95]);
        scale[0] = lo;
        scale[1] = hi;
        scale[2] = fmaxf(hi - lo, 1.0f);
    }
}

// ---------------------------------------------------------------------------
// per-token loss
// ---------------------------------------------------------------------------
__device__ __forceinline__ float twohot_nll(const float* svl, const float* sbins,
                                            float logZ, float y)
{
    y = fminf(fmaxf(y, sbins[0]), sbins[NBc - 1]);
    int lo = 0, hi = NBc - 1;
    while (hi > lo) {
        int mid = (lo + hi) >> 1;
        if (sbins[mid] >= y) hi = mid; else lo = mid + 1;
    }
    int k = hi - 1;
    if (k < 0) k = 0;
    if (k > NBc - 2) k = NBc - 2;
    float bl = sbins[k], bh = sbins[k + 1];
    float w = (y - bl) / (bh - bl);
    w = fminf(fmaxf(w, 0.f), 1.f);
    float l0 = svl[k] - logZ, l1 = svl[k + 1] - logZ;
    return -((1.f - w) * l0 + w * l1);
}

__global__ __launch_bounds__(256) void loss_kernel(
    const float* __restrict__ vlog, const float* __restrict__ plog,
    const float* __restrict__ smean, const float* __restrict__ ret,
    const float* __restrict__ wgt, const int* __restrict__ act,
    const float* __restrict__ scale, float* __restrict__ loss)
{
    __shared__ float sbins[NBc];
    __shared__ float svl[NBc];
    __shared__ float sred[8];
    __shared__ float sres[4];

    int i = blockIdx.x;
    int b = i / TM1, t = i - b * TM1;
    int row = b * Tc + t;
    int tid = threadIdx.x;

    if (tid < NBc) {
        sbins[tid] = bin_val(tid);
        svl[tid] = vlog[(size_t)row * NBc + tid];
    }
    __syncthreads();

    float v = (tid < NBc) ? svl[tid] : -3.4e38f;
    #pragma unroll
    for (int o = 16; o; o >>= 1) v = fmaxf(v, __shfl_xor_sync(0xffffffffu, v, o));
    if ((tid & 31) == 0) sred[tid >> 5] = v;
    __syncthreads();
    if (tid < 32) {
        float m = (tid < 8) ? sred[tid] : -3.4e38f;
        #pragma unroll
        for (int o = 4; o; o >>= 1) m = fmaxf(m, __shfl_xor_sync(0xffffffffu, m, o));
        if (tid == 0) sres[0] = m;
    }
    __syncthreads();
    float M = sres[0];
    float e = (tid < NBc) ? expf(svl[tid] - M) : 0.f;
    #pragma unroll
    for (int o = 16; o; o >>= 1) e += __shfl_xor_sync(0xffffffffu, e, o);
    if ((tid & 31) == 0) sred[tid >> 5] = e;
    __syncthreads();
    if (tid < 32) {
        float s = (tid < 8) ? sred[tid] : 0.f;
        #pragma unroll
        for (int o = 4; o; o >>= 1) s += __shfl_xor_sync(0xffffffffu, s, o);
        if (tid == 0) sres[0] = M + logf(s);
    }
    __syncthreads();
    float logZ = sres[0];

    if (tid < 32) {
        float p0 = plog[(size_t)row * Ac + tid];
        float p1 = plog[(size_t)row * Ac + tid + 32];
        float m = fmaxf(p0, p1);
        #pragma unroll
        for (int o = 16; o; o >>= 1) m = fmaxf(m, __shfl_xor_sync(0xffffffffu, m, o));
        float e0 = expf(p0 - m), e1 = expf(p1 - m);
        float s = e0 + e1;
        #pragma unroll
        for (int o = 16; o; o >>= 1) s += __shfl_xor_sync(0xffffffffu, s, o);
        float inv = 1.0f / s;
        float pr0 = 0.99f * e0 * inv + UNIMIX_A;
        float pr1 = 0.99f * e1 * inv + UNIMIX_A;
        float lp0 = logf(pr0), lp1 = logf(pr1);
        float entp = -(pr0 * lp0 + pr1 * lp1);
        #pragma unroll
        for (int o = 16; o; o >>= 1) entp += __shfl_xor_sync(0xffffffffu, entp, o);
        int a = act[row];
        float lpi = (a == tid) ? lp0 : ((a == tid + 32) ? lp1 : 0.f);
        #pragma unroll
        for (int o = 16; o; o >>= 1) lpi += __shfl_xor_sync(0xffffffffu, lpi, o);
        if (tid == 0) { sres[1] = entp; sres[2] = lpi; }
    }
    __syncthreads();

    if (tid == 0) {
        float reti = ret[i];
        float sm = smean[row];
        float rscale = scale[2];
        float adv = (reti - sm) / rscale;
        float wt = wgt[i];
        float pl = wt * -(sres[2] * adv + ACTENT_C * sres[1]);
        float vl = twohot_nll(svl, sbins, logZ, reti) + twohot_nll(svl, sbins, logZ, sm);
        loss[i] = pl + wt * vl;
    }
}

// ---------------------------------------------------------------------------
// final reduction
// ---------------------------------------------------------------------------
__global__ __launch_bounds__(1024) void reduce_kernel(
    const float* __restrict__ loss, float* __restrict__ out)
{
    __shared__ double sd[32];
    double s = 0.0;
    for (int i = threadIdx.x; i < NLOSS; i += 1024) s += (double)loss[i];
    #pragma unroll
    for (int o = 16; o; o >>= 1) s += __shfl_xor_sync(0xffffffffu, s, o);
    if ((threadIdx.x & 31) == 0) sd[threadIdx.x >> 5] = s;
    __syncthreads();
    if (threadIdx.x == 0) {
        double tot = 0.0;
        #pragma unroll
        for (int w = 0; w < 32; w++) tot += sd[w];
        out[0] = (float)(tot / (double)NLOSS);
    }
}

// ---------------------------------------------------------------------------
// host
// ---------------------------------------------------------------------------
struct NetBufs {
    __nv_bfloat16 *whi, *wlo;   // 5 x 1024 x 1024
    __nv_bfloat16 *hhi, *hlo;   // head, padded rows
};

static void run_net_gemms(const float* gn, const float* Hb, const NetBufs& nb,
                          int headM, int headTiles,
                          const __nv_bfloat16* fhi, const __nv_bfloat16* flo,
                          float* h0, __nv_bfloat16* ahi, __nv_bfloat16* alo,
                          float* outLogits)
{
    dim3 gU(NTOK / 128, 8);
    tc_gemm<<<gU, 256, SMEM_B>>>(fhi, flo, nb.whi, nb.wlo, nullptr, h0, Uc);
    rmsnorm_silu_split_kernel<<<NTOK, 256>>>(h0, gn, ahi, alo);
    for (int i = 0; i < 4; i++) {
        tc_gemm<<<gU, 256, SMEM_B>>>(ahi, alo,
                                     nb.whi + (size_t)(i + 1) * Uc * Uc,
                                     nb.wlo + (size_t)(i + 1) * Uc * Uc,
                                     nullptr, h0, Uc);
        rmsnorm_silu_split_kernel<<<NTOK, 256>>>(h0, gn + (size_t)(i + 1) * Uc, ahi, alo);
    }
    dim3 gH(NTOK / 128, headTiles);
    tc_gemm<<<gH, 256, SMEM_B>>>(ahi, alo, nb.hhi, nb.hlo, Hb, outLogits, headM);
}

extern "C" void kernel_launch(void* const* d_in, const int* in_sizes, int n_in,
                              void* d_out, int out_size)
{
    const float* feat   = (const float*)d_in[0];
    const float* reward = (const float*)d_in[1];
    const float* cont   = (const float*)d_in[2];
    const int*   act    = (const int*)  d_in[3];
    const float* pW_in  = (const float*)d_in[4];
    const float* pW_hid = (const float*)d_in[5];
    const float* p_gn   = (const float*)d_in[6];
    const float* pHw    = (const float*)d_in[7];
    const float* pHb    = (const float*)d_in[8];
    const float* vW_in  = (const float*)d_in[9];
    const float* vW_hid = (const float*)d_in[10];
    const float* v_gn   = (const float*)d_in[11];
    const float* vHw    = (const float*)d_in[12];
    const float* vHb    = (const float*)d_in[13];
    const float* sW_in  = (const float*)d_in[14];
    const float* sW_hid = (const float*)d_in[15];
    const float* s_gn   = (const float*)d_in[16];
    const float* sHw    = (const float*)d_in[17];
    const float* sHb    = (const float*)d_in[18];

    float *h0, *vlog, *slog, *plg, *smean, *ret, *wgt, *scale, *loss;
    __nv_bfloat16 *fhi, *flo, *ahi, *alo;
    NetBufs nbv, nbs, nbp;
    cudaGetSymbolAddress((void**)&h0, g_h0);
    cudaGetSymbolAddress((void**)&fhi, g_fhi);
    cudaGetSymbolAddress((void**)&flo, g_flo);
    cudaGetSymbolAddress((void**)&ahi, g_ahi);
    cudaGetSymbolAddress((void**)&alo, g_alo);
    cudaGetSymbolAddress((void**)&vlog, g_vlog);
    cudaGetSymbolAddress((void**)&slog, g_slog);
    cudaGetSymbolAddress((void**)&plg, g_plog);
    cudaGetSymbolAddress((void**)&smean, g_smean);
    cudaGetSymbolAddress((void**)&ret, g_ret);
    cudaGetSymbolAddress((void**)&wgt, g_wgt);
    cudaGetSymbolAddress((void**)&scale, g_scale);
    cudaGetSymbolAddress((void**)&loss, g_loss);
    cudaGetSymbolAddress((void**)&nbv.whi, g_wv_hi);
    cudaGetSymbolAddress((void**)&nbv.wlo, g_wv_lo);
    cudaGetSymbolAddress((void**)&nbs.whi, g_ws_hi);
    cudaGetSymbolAddress((void**)&nbs.wlo, g_ws_lo);
    cudaGetSymbolAddress((void**)&nbp.whi, g_wp_hi);
    cudaGetSymbolAddress((void**)&nbp.wlo, g_wp_lo);
    cudaGetSymbolAddress((void**)&nbv.hhi, g_hv_hi);
    cudaGetSymbolAddress((void**)&nbv.hlo, g_hv_lo);
    cudaGetSymbolAddress((void**)&nbs.hhi, g_hs_hi);
    cudaGetSymbolAddress((void**)&nbs.hlo, g_hs_lo);
    cudaGetSymbolAddress((void**)&nbp.hhi, g_hp_hi);
    cudaGetSymbolAddress((void**)&nbp.hlo, g_hp_lo);

    cudaFuncSetAttribute(tc_gemm, cudaFuncAttributeMaxDynamicSharedMemorySize, SMEM_B);
    cudaFuncSetAttribute(percentile_kernel,
                         cudaFuncAttributeMaxDynamicSharedMemorySize, 131072);

    dim3 tb(32, 8);
    // net v prep first so launch #5 (ncu -s 5) is a steady-state tc_gemm:
    // 0: split_wt5(v)  1: split_wt(head v)  2: split_act
    // 3: tc_gemm L0    4: rmsnorm           5: tc_gemm L1  <- profiled
    split_wt5_kernel<<<dim3(32, 32, 5), tb>>>(vW_in, vW_hid, nbv.whi, nbv.wlo);
    split_wt_kernel<<<dim3(32, 8), tb>>>(vHw, nbv.hhi, nbv.hlo, NBc);
    split_act_kernel<<<NTOK, 256>>>(feat, fhi, flo);
    run_net_gemms(v_gn, vHb, nbv, NBc, 2, fhi, flo, h0, ahi, alo, vlog);

    split_wt5_kernel<<<dim3(32, 32, 5), tb>>>(sW_in, sW_hid, nbs.whi, nbs.wlo);
    split_wt_kernel<<<dim3(32, 8), tb>>>(sHw, nbs.hhi, nbs.hlo, NBc);
    run_net_gemms(s_gn, sHb, nbs, NBc, 2, fhi, flo, h0, ahi, alo, slog);
    slowmean_kernel<<<NTOK, 256>>>(slog, smean);

    split_wt5_kernel<<<dim3(32, 32, 5), tb>>>(pW_in, pW_hid, nbp.whi, nbp.wlo);
    split_wt_kernel<<<dim3(32, 2), tb>>>(pHw, nbp.hhi, nbp.hlo, Ac);
    run_net_gemms(p_gn, pHb, nbp, Ac, 1, fhi, flo, h0, ahi, alo, plg);

    lamret_kernel<<<1, 64>>>(reward, cont, smean, ret, wgt);
    percentile_kernel<<<1, 1024, 131072>>>(ret, scale);
    loss_kernel<<<NLOSS, 256>>>(vlog, plg, smean, ret, wgt, act, scale, loss);
    reduce_kernel<<<1, 1024>>>(loss, (float*)d_out);
}